// round 12
// baseline (speedup 1.0000x reference)
#include <cuda_runtime.h>
#include <cuda_fp16.h>
#include <cstdint>

#define Df 4096
#define Lf 24
#define Nf 576
#define Tf 128
#define REDf 1024
#define MROWS (Lf*Nf)
#define NSTEP 23
#define FOCUS 22
#define GY 16

#define BM 256
#define NCH 128          // k-chunks of 32
#define STG 4
#define STGB 40960       // bytes per stage (A 20480 + B 20480)
#define XN (MROWS*Df)
#define WN (Df*Df)

// ---------------- device scratch ----------------
__device__ __half g_Xh[XN];
__device__ __half g_Wkh[WN];
__device__ float g_tgm[Df];
__device__ float g_tg[Df];
__device__ float g_y[Lf][Df];
__device__ float g_pres[NSTEP][REDf];
__device__ float g_c[Df];
__device__ float g_sc[Df];
__device__ float g_s[REDf];
__device__ float g_qraw[Df];
__device__ float g_wq[Df];
__device__ float g_Bs, g_Cs;
__device__ float g_ap[8][Df];
__device__ float g_vp[8][Df];
__device__ float g_a[Df];
__device__ float g_v[Df];
__device__ float g_S1[MROWS];
__device__ float g_S2part[GY][MROWS];
__device__ float g_S3[MROWS];
__device__ float g_zs[Lf][Nf];
__device__ float g_topv[Lf][64];
__device__ int   g_topi[Lf][64];
__device__ int   g_sel_li[64];
__device__ int   g_sel_idx[64];

// ---------------- helpers ----------------
__device__ __forceinline__ float warpsum(float v) {
    #pragma unroll
    for (int o = 16; o; o >>= 1) v += __shfl_xor_sync(0xffffffffu, v, o);
    return v;
}

__device__ __forceinline__ float blocksum(float v, float* red) {
    int tid = threadIdx.x, ln = tid & 31, w = tid >> 5, nw = blockDim.x >> 5;
    float s = warpsum(v);
    if (ln == 0) red[w] = s;
    __syncthreads();
    if (w == 0) {
        float r = (ln < nw) ? red[ln] : 0.f;
        r = warpsum(r);
        if (ln == 0) red[0] = r;
    }
    __syncthreads();
    float out = red[0];
    __syncthreads();
    return out;
}

__device__ __forceinline__ float sigm_(float x) { return 1.f / (1.f + expf(-x)); }

__device__ __forceinline__ uint32_t smem_u32(const void* p) {
    uint32_t a;
    asm("{ .reg .u64 t; cvta.to.shared.u64 t, %1; cvt.u32.u64 %0, t; }" : "=r"(a) : "l"(p));
    return a;
}

__device__ __forceinline__ void mma_f16(float c[4], uint32_t a0, uint32_t a1,
                                        uint32_t a2, uint32_t a3,
                                        uint32_t b0, uint32_t b1) {
    asm volatile(
        "mma.sync.aligned.m16n8k16.row.col.f32.f16.f16.f32 "
        "{%0,%1,%2,%3}, {%4,%5,%6,%7}, {%8,%9}, {%0,%1,%2,%3};\n"
        : "+f"(c[0]), "+f"(c[1]), "+f"(c[2]), "+f"(c[3])
        : "r"(a0), "r"(a1), "r"(a2), "r"(a3), "r"(b0), "r"(b1));
}

#define LDSM4(r0, r1, r2, r3, addr) \
    asm volatile("ldmatrix.sync.aligned.m8n8.x4.shared.b16 {%0,%1,%2,%3}, [%4];" \
                 : "=r"(r0), "=r"(r1), "=r"(r2), "=r"(r3) : "r"(addr))

#define CPA16(dst, src) \
    asm volatile("cp.async.cg.shared.global [%0], [%1], 16;" :: "r"(dst), "l"(src) : "memory")
#define CPA_COMMIT() asm volatile("cp.async.commit_group;" ::: "memory")
#define CPA_WAIT2()  asm volatile("cp.async.wait_group 2;" ::: "memory")

__device__ __forceinline__ uint32_t pack_h2(float lo, float hi) {
    __half2 h = __floats2half2_rn(lo, hi);
    return reinterpret_cast<uint32_t&>(h);
}

// ---------------- conversion (fp32 -> fp16), one pass ----------------
__global__ void k_conv(const float* __restrict__ X, const float* __restrict__ Wk) {
    size_t i = ((size_t)blockIdx.x * 256 + threadIdx.x) * 8;
    const float* src; __half* dst; size_t off;
    if (i < (size_t)XN) { src = X; dst = g_Xh; off = i; }
    else { src = Wk; dst = g_Wkh; off = i - (size_t)XN; }
    float4 a = *(const float4*)(src + off);
    float4 b = *(const float4*)(src + off + 4);
    uint4 o;
    o.x = pack_h2(a.x, a.y); o.y = pack_h2(a.z, a.w);
    o.z = pack_h2(b.x, b.y); o.w = pack_h2(b.z, b.w);
    *(uint4*)(dst + off) = o;
}

// ---------------- small kernels ----------------
__global__ void k_init() {
    int d = blockIdx.x * blockDim.x + threadIdx.x;
    if (d < Df) { g_c[d] = 0.f; g_sc[d] = 0.5f; }
}

__global__ void k_tg1(const float* __restrict__ text) {
    int d = blockIdx.x * blockDim.x + threadIdx.x;
    float s = 0.f;
    for (int t = 0; t < Tf; t++) s += text[(size_t)t * Df + d];
    g_tgm[d] = s * (1.0f / Tf);
}

__global__ void k_tg2() {
    __shared__ float red[32];
    int tid = threadIdx.x;
    float v[4];
    #pragma unroll
    for (int j = 0; j < 4; j++) v[j] = g_tgm[tid + j * 1024];
    float tot = blocksum(v[0] + v[1] + v[2] + v[3], red);
    float mu = tot * (1.f / Df);
    float q = 0.f;
    #pragma unroll
    for (int j = 0; j < 4; j++) { float dd = v[j] - mu; q += dd * dd; }
    float var = blocksum(q, red) * (1.f / Df);
    float inv = rsqrtf(var + 1e-5f);
    #pragma unroll
    for (int j = 0; j < 4; j++) g_tg[tid + j * 1024] = (v[j] - mu) * inv;
}

__global__ void k_y(const float* __restrict__ proj) {
    int l = blockIdx.y;
    int d = blockIdx.x * 256 + threadIdx.x;
    const float* p = proj + (size_t)l * Nf * Df + d;
    float s = 0.f;
    for (int n = 0; n < Nf; n++) s += p[(size_t)n * Df];
    g_y[l][d] = s * (1.0f / Nf);
}

__global__ void k_pres(const float* __restrict__ W1w, const float* __restrict__ W1b) {
    int warp = (blockIdx.x * blockDim.x + threadIdx.x) >> 5;
    int lane = threadIdx.x & 31;
    if (warp >= REDf) return;
    const float* rowY = W1w + (size_t)warp * (3 * Df) + Df;
    const float* rowT = rowY + Df;
    float accT = 0.f;
    float accL[NSTEP];
    #pragma unroll
    for (int l = 0; l < NSTEP; l++) accL[l] = 0.f;
    for (int d = lane; d < Df; d += 32) {
        float wy = rowY[d];
        float wt = rowT[d];
        accT += wt * g_tg[d];
        #pragma unroll
        for (int l = 0; l < NSTEP; l++) accL[l] += wy * g_y[l][d];
    }
    accT = warpsum(accT);
    #pragma unroll
    for (int l = 0; l < NSTEP; l++) accL[l] = warpsum(accL[l]);
    if (lane == 0) {
        float base = W1b[warp] + accT;
        #pragma unroll
        for (int l = 0; l < NSTEP; l++) g_pres[l][warp] = base + accL[l];
    }
}

// ------- fused S2 GEMM: 256x256 tile, fp16, cp.async + ldmatrix, 4-stage -----
__global__ void __launch_bounds__(512, 1) k_s2h() {
    extern __shared__ __half sh[];
    uint32_t sbase = smem_u32(sh);
    int tid = threadIdx.x;
    int lane = tid & 31, warp = tid >> 5;
    int wm = warp >> 2, wn = warp & 3;   // 4 m-warps x 4 n-warps
    int g = lane >> 2;
    int row_block = blockIdx.x * BM;
    int e0 = blockIdx.y * 256;
    int seg0 = tid * 2;

    // ldmatrix per-lane addressing (proven mapping)
    int arow = lane & 15;
    int akoff = (lane >> 4) * 8;              // halves
    int brow = (lane & 7) + ((lane & 16) >> 1);
    int bkoff = (lane & 8) ? 8 : 0;           // halves

    float acc[4][8][4];
    #pragma unroll
    for (int mt = 0; mt < 4; mt++)
        #pragma unroll
        for (int ni = 0; ni < 8; ni++)
            #pragma unroll
            for (int r = 0; r < 4; r++) acc[mt][ni][r] = 0.f;

    auto issue = [&](int c) {
        int sl = c & (STG - 1);
        int kb = c * 32;                     // half offset within row
        #pragma unroll
        for (int i = 0; i < 2; i++) {
            int seg = seg0 + i;
            int row = seg >> 2, q = seg & 3;   // row 0..255
            const __half* sa = g_Xh + (size_t)(row_block + row) * Df + kb + q * 8;
            uint32_t da = sbase + (uint32_t)(sl * STGB + row * 80 + q * 16);
            CPA16(da, sa);
            const __half* sb = g_Wkh + (size_t)(e0 + row) * Df + kb + q * 8;
            uint32_t db = sbase + (uint32_t)(sl * STGB + 20480 + row * 80 + q * 16);
            CPA16(db, sb);
        }
    };

    issue(0); CPA_COMMIT();
    issue(1); CPA_COMMIT();
    issue(2); CPA_COMMIT();

    for (int c = 0; c < NCH; ++c) {
        CPA_WAIT2();                      // 3 pending -> oldest (chunk c) done
        __syncthreads();
        int sl = c & (STG - 1);
        uint32_t abase = sbase + sl * STGB;
        uint32_t bbase = abase + 20480;

        #pragma unroll
        for (int kk = 0; kk < 2; kk++) {
            uint32_t a[4][4];
            #pragma unroll
            for (int mt = 0; mt < 4; mt++) {
                uint32_t aaddr = abase +
                    (uint32_t)((wm * 64 + mt * 16 + arow) * 80 + (kk * 16 + akoff) * 2);
                LDSM4(a[mt][0], a[mt][1], a[mt][2], a[mt][3], aaddr);
            }
            #pragma unroll
            for (int p = 0; p < 4; p++) {
                uint32_t b[4];
                uint32_t baddr = bbase +
                    (uint32_t)((wn * 64 + p * 16 + brow) * 80 + (kk * 16 + bkoff) * 2);
                LDSM4(b[0], b[1], b[2], b[3], baddr);
                #pragma unroll
                for (int mt = 0; mt < 4; mt++) {
                    mma_f16(acc[mt][2 * p],     a[mt][0], a[mt][1], a[mt][2], a[mt][3], b[0], b[1]);
                    mma_f16(acc[mt][2 * p + 1], a[mt][0], a[mt][1], a[mt][2], a[mt][3], b[2], b[3]);
                }
            }
        }

        if (c + 3 < NCH) issue(c + 3);
        CPA_COMMIT();
    }

    // squares + reductions
    float s2p[8];
    #pragma unroll
    for (int mt = 0; mt < 4; mt++) {
        float p0 = 0.f, p1 = 0.f;
        #pragma unroll
        for (int ni = 0; ni < 8; ni++) {
            p0 += acc[mt][ni][0] * acc[mt][ni][0] + acc[mt][ni][1] * acc[mt][ni][1];
            p1 += acc[mt][ni][2] * acc[mt][ni][2] + acc[mt][ni][3] * acc[mt][ni][3];
        }
        s2p[mt * 2 + 0] = p0;   // row wm*64 + mt*16 + g
        s2p[mt * 2 + 1] = p1;   // row wm*64 + mt*16 + g + 8
    }
    #pragma unroll
    for (int j = 0; j < 8; j++) {
        s2p[j] += __shfl_xor_sync(0xffffffffu, s2p[j], 1);
        s2p[j] += __shfl_xor_sync(0xffffffffu, s2p[j], 2);
    }
    __syncthreads();                       // stage smem reads done; reuse
    float* s2sh = (float*)sh;              // [4 nwarps][256 rows]
    if ((lane & 3) == 0) {
        #pragma unroll
        for (int mt = 0; mt < 4; mt++) {
            int r = wm * 64 + mt * 16 + g;
            s2sh[wn * BM + r]     = s2p[mt * 2 + 0];
            s2sh[wn * BM + r + 8] = s2p[mt * 2 + 1];
        }
    }
    __syncthreads();
    if (tid < BM) {
        float s = s2sh[tid] + s2sh[BM + tid] + s2sh[2 * BM + tid] + s2sh[3 * BM + tid];
        g_S2part[blockIdx.y][row_block + tid] = s;
    }
}

// ---------------- DSU / q pipeline ----------------
__global__ void k_step_s(const float* __restrict__ W1w, int l) {
    int warp = (blockIdx.x * 256 + threadIdx.x) >> 5;
    int lane = threadIdx.x & 31;
    const float4* row = (const float4*)(W1w + (size_t)warp * (3 * Df));
    const float4* scv = (const float4*)g_sc;
    float acc = 0.f;
    for (int i = lane; i < Df / 4; i += 32) {
        float4 w = row[i]; float4 s = scv[i];
        acc += w.x * s.x + w.y * s.y + w.z * s.z + w.w * s.w;
    }
    acc = warpsum(acc);
    if (lane == 0) {
        float v = g_pres[l][warp] + acc;
        g_s[warp] = v > 0.f ? v : 0.f;
    }
}

__global__ void k_step_c(const float* __restrict__ Wc, const float* __restrict__ Wcb,
                         const float* __restrict__ Wi, const float* __restrict__ Wib,
                         const float* __restrict__ Wf, const float* __restrict__ Wfb,
                         const float* __restrict__ bc, const float* __restrict__ bi,
                         const float* __restrict__ bf) {
    int d = (blockIdx.x * 256 + threadIdx.x) >> 5;
    int lane = threadIdx.x & 31;
    const float4* rc = (const float4*)(Wc + (size_t)d * REDf);
    const float4* ri = (const float4*)(Wi + (size_t)d * REDf);
    const float4* rf = (const float4*)(Wf + (size_t)d * REDf);
    const float4* sv = (const float4*)g_s;
    float ac = 0.f, ai = 0.f, af = 0.f;
    for (int i = lane; i < REDf / 4; i += 32) {
        float4 s = sv[i];
        float4 c4 = rc[i]; ac += c4.x * s.x + c4.y * s.y + c4.z * s.z + c4.w * s.w;
        float4 i4 = ri[i]; ai += i4.x * s.x + i4.y * s.y + i4.z * s.z + i4.w * s.w;
        float4 f4 = rf[i]; af += f4.x * s.x + f4.y * s.y + f4.z * s.z + f4.w * s.w;
    }
    ac = warpsum(ac); ai = warpsum(ai); af = warpsum(af);
    if (lane == 0) {
        float ct = tanhf(ac + Wcb[d] + bc[d]);
        float iv = sigm_(ai + Wib[d] + bi[d]);
        float fv = sigm_(af + Wfb[d] + bf[d]);
        float cn = fv * g_c[d] + iv * ct;
        g_c[d] = cn;
        g_sc[d] = sigm_(cn);
    }
}

__global__ void k_qraw(const float* __restrict__ Wq) {
    int e = (blockIdx.x * 256 + threadIdx.x) >> 5;
    int lane = threadIdx.x & 31;
    const float4* row = (const float4*)(Wq + (size_t)e * Df);
    const float4* cv = (const float4*)g_c;
    float acc = 0.f;
    for (int i = lane; i < Df / 4; i += 32) {
        float4 w = row[i]; float4 c4 = cv[i];
        acc += w.x * c4.x + w.y * c4.y + w.z * c4.z + w.w * c4.w;
    }
    acc = warpsum(acc);
    if (lane == 0) g_qraw[e] = acc;
}

__global__ void k_qln(const float* __restrict__ lnw, const float* __restrict__ lnb) {
    __shared__ float red[32];
    int tid = threadIdx.x;
    float v[4];
    #pragma unroll
    for (int j = 0; j < 4; j++) v[j] = g_qraw[tid + j * 1024];
    float tot = blocksum(v[0] + v[1] + v[2] + v[3], red);
    float mu = tot * (1.f / Df);
    float q = 0.f;
    #pragma unroll
    for (int j = 0; j < 4; j++) { float dd = v[j] - mu; q += dd * dd; }
    float var = blocksum(q, red) * (1.f / Df);
    float inv = rsqrtf(var + 1e-5f);
    float Bp = 0.f, Cp = 0.f;
    #pragma unroll
    for (int j = 0; j < 4; j++) {
        int e = tid + j * 1024;
        float w = lnw[e], b = lnb[e];
        float qv = (v[j] - mu) * inv * w + b;
        float wq = w * qv;
        g_wq[e] = wq;
        Bp += wq;
        Cp += b * qv;
    }
    float Bt = blocksum(Bp, red);
    float Ct = blocksum(Cp, red);
    if (tid == 0) { g_Bs = Bt; g_Cs = Ct; }
}

__global__ void k_av1(const float* __restrict__ Wk) {
    int d = blockIdx.x * 256 + threadIdx.x;
    int ep = blockIdx.y;
    float sa = 0.f, sv = 0.f;
    int e0 = ep * (Df / 8);
    for (int e = e0; e < e0 + Df / 8; e++) {
        float wk = __ldg(Wk + (size_t)e * Df + d);
        sa += wk;
        sv += g_wq[e] * wk;
    }
    g_ap[ep][d] = sa;
    g_vp[ep][d] = sv;
}

__global__ void k_av2() {
    int d = blockIdx.x * 256 + threadIdx.x;
    float sa = 0.f, sv = 0.f;
    #pragma unroll
    for (int p = 0; p < 8; p++) { sa += g_ap[p][d]; sv += g_vp[p][d]; }
    g_a[d] = sa;
    g_v[d] = sv;
}

__global__ void k_s13(const float* __restrict__ proj) {
    int row = (blockIdx.x * 256 + threadIdx.x) >> 5;
    int lane = threadIdx.x & 31;
    const float4* x = (const float4*)(proj + (size_t)row * Df);
    const float4* av = (const float4*)g_a;
    const float4* vv = (const float4*)g_v;
    float s1 = 0.f, s3 = 0.f;
    for (int i = lane; i < Df / 4; i += 32) {
        float4 xx = x[i];
        float4 aa = av[i];
        float4 v4 = vv[i];
        s1 += xx.x * aa.x + xx.y * aa.y + xx.z * aa.z + xx.w * aa.w;
        s3 += xx.x * v4.x + xx.y * v4.y + xx.z * v4.z + xx.w * v4.w;
    }
    s1 = warpsum(s1); s3 = warpsum(s3);
    if (lane == 0) { g_S1[row] = s1; g_S3[row] = s3; }
}

// ---------------- scores, z, topk, select, gather ----------------
__global__ void k_score() {
    int l = blockIdx.x;
    __shared__ float sc[Nf];
    __shared__ float red[32];
    int tid = threadIdx.x;
    float B = g_Bs, C = g_Cs;
    float part = 0.f;
    float loc[3];
    #pragma unroll
    for (int j = 0; j < 3; j++) {
        int n = tid + j * 192;
        int i = l * Nf + n;
        float s2 = 0.f;
        #pragma unroll
        for (int p = 0; p < GY; p++) s2 += g_S2part[p][i];
        float mu = g_S1[i] * (1.f / Df);
        float var = s2 * (1.f / Df) - mu * mu;
        float s = (g_S3[i] - mu * B) / sqrtf(var + 1e-5f) + C;
        sc[n] = s;
        loc[j] = s;
        part += s;
    }
    float mu_s = blocksum(part, red) * (1.f / Nf);
    float q = 0.f;
    #pragma unroll
    for (int j = 0; j < 3; j++) { float dd = loc[j] - mu_s; q += dd * dd; }
    float sd = sqrtf(blocksum(q, red) * (1.f / Nf));
    float inv = 1.f / (sd + 1e-6f);
    #pragma unroll
    for (int j = 0; j < 3; j++) {
        int n = tid + j * 192;
        g_zs[l][n] = (sc[n] - mu_s) * inv;
    }
}

__global__ void k_topk() {
    int l = blockIdx.x;
    __shared__ float sv[Nf];
    __shared__ float bv[8];
    __shared__ int bidx[8];
    int tid = threadIdx.x;
    int warp = tid >> 5, lane = tid & 31;
    for (int n = tid; n < Nf; n += 256) sv[n] = g_zs[l][n];
    __syncthreads();
    for (int t = 0; t < 64; t++) {
        float best = -3.4e38f;
        int besti = Nf;
        for (int n = tid; n < Nf; n += 256) {
            float v = sv[n];
            if (v > best || (v == best && n < besti)) { best = v; besti = n; }
        }
        #pragma unroll
        for (int o = 16; o; o >>= 1) {
            float ov = __shfl_xor_sync(0xffffffffu, best, o);
            int oi = __shfl_xor_sync(0xffffffffu, besti, o);
            if (ov > best || (ov == best && oi < besti)) { best = ov; besti = oi; }
        }
        if (lane == 0) { bv[warp] = best; bidx[warp] = besti; }
        __syncthreads();
        if (tid == 0) {
            float fb = bv[0]; int fi = bidx[0];
            #pragma unroll
            for (int w = 1; w < 8; w++)
                if (bv[w] > fb || (bv[w] == fb && bidx[w] < fi)) { fb = bv[w]; fi = bidx[w]; }
            g_topv[l][t] = fb;
            g_topi[l][t] = fi;
            sv[fi] = -3.4e38f;
        }
        __syncthreads();
    }
}

__global__ void k_select() {
    if (threadIdx.x != 0 || blockIdx.x != 0) return;
    float conf[Lf];
    for (int l = 0; l < Lf; l++) conf[l] = g_topv[l][0];

    int kper[Lf];
    for (int l = 0; l < Lf; l++) kper[l] = 0;
    kper[FOCUS] = 64;
    int rest = 64;

    int other[Lf]; int no = 0;
    for (int l = 0; l < Lf; l++)
        if (l != FOCUS && conf[l] > 2.0f) other[no++] = l;

    if (no > 0 && rest > 0) {
        float w[Lf];
        float mx = -3.4e38f;
        for (int j = 0; j < no; j++) if (conf[other[j]] > mx) mx = conf[other[j]];
        float sum = 0.f;
        for (int j = 0; j < no; j++) { w[j] = expf(conf[other[j]] - mx); sum += w[j]; }
        for (int j = 0; j < no; j++) w[j] /= sum;
        long long alloc[Lf]; long long asum = 0;
        for (int j = 0; j < no; j++) { alloc[j] = (long long)floorf(w[j] * (float)rest); asum += alloc[j]; }
        long long rem = rest - asum;
        bool used[Lf];
        for (int j = 0; j < no; j++) used[j] = false;
        for (int t = 0; t < no && rem > 0; t++) {
            int best = -1;
            for (int j = 0; j < no; j++)
                if (!used[j] && (best < 0 || w[j] > w[best])) best = j;
            used[best] = true;
            alloc[best]++; rem--;
        }
        for (int j = 0; j < no; j++)
            if (alloc[j] > 0) {
                int v = (int)alloc[j];
                kper[other[j]] = v < Nf ? v : Nf;
            }
    }

    float sc[192]; int fli[192], fidx[192]; int M = 0;
    for (int l = 0; l < Lf; l++) {
        int kl = kper[l];
        for (int t = 0; t < kl; t++) {
            fli[M] = l; fidx[M] = g_topi[l][t]; sc[M] = g_topv[l][t]; M++;
        }
    }

    int final_k = M < 64 ? M : 64;
    int focus_min = final_k < 32 ? final_k : 32;

    int sel[64]; int ns = 0;
    bool taken[192];
    for (int m = 0; m < M; m++) taken[m] = false;

    for (int t = 0; t < focus_min; t++) {
        int best = -1;
        for (int m = 0; m < M; m++)
            if (fli[m] == FOCUS && !taken[m] && (best < 0 || sc[m] > sc[best])) best = m;
        if (best < 0) break;
        taken[best] = true; sel[ns++] = best;
    }
    int remain = final_k - ns;
    for (int t = 0; t < remain; t++) {
        int best = -1;
        for (int m = 0; m < M; m++)
            if (!taken[m] && (best < 0 || sc[m] > sc[best])) best = m;
        if (best < 0) break;
        taken[best] = true; sel[ns++] = best;
    }
    for (int i = 0; i < ns; i++) {
        int bj = i;
        for (int j = i + 1; j < ns; j++)
            if (sc[sel[j]] > sc[sel[bj]]) bj = j;
        int tmp = sel[i]; sel[i] = sel[bj]; sel[bj] = tmp;
    }
    for (int i = 0; i < ns; i++) {
        g_sel_li[i] = fli[sel[i]];
        g_sel_idx[i] = fidx[sel[i]];
    }
}

__global__ void k_gather(const float* __restrict__ proj, float* __restrict__ out) {
    int j = blockIdx.x;
    int li = g_sel_li[j], idx = g_sel_idx[j];
    const float4* src = (const float4*)(proj + ((size_t)li * Nf + idx) * Df);
    float4* dst = (float4*)(out + (size_t)j * Df);
    for (int i = threadIdx.x; i < Df / 4; i += blockDim.x) dst[i] = src[i];
}

// ---------------- launch ----------------
extern "C" void kernel_launch(void* const* d_in, const int* in_sizes, int n_in,
                              void* d_out, int out_size) {
    const float* text = (const float*)d_in[0];
    const float* proj = (const float*)d_in[1];
    const float* Wq   = (const float*)d_in[2];
    const float* Wk   = (const float*)d_in[3];
    const float* lnw  = (const float*)d_in[4];
    const float* lnb  = (const float*)d_in[5];
    const float* W1w  = (const float*)d_in[6];
    const float* W1b  = (const float*)d_in[7];
    const float* Wcw  = (const float*)d_in[8];
    const float* Wcb  = (const float*)d_in[9];
    const float* Wiw  = (const float*)d_in[10];
    const float* Wib  = (const float*)d_in[11];
    const float* Wfw  = (const float*)d_in[12];
    const float* Wfb  = (const float*)d_in[13];
    const float* bc   = (const float*)d_in[14];
    const float* bi   = (const float*)d_in[15];
    const float* bf   = (const float*)d_in[16];
    float* out = (float*)d_out;

    static cudaStream_t s_side = nullptr;
    static cudaEvent_t ev_fork = nullptr, ev_join = nullptr;
    static bool attr_done = false;
    if (s_side == nullptr) {
        cudaStreamCreateWithFlags(&s_side, cudaStreamNonBlocking);
        cudaEventCreateWithFlags(&ev_fork, cudaEventDisableTiming);
        cudaEventCreateWithFlags(&ev_join, cudaEventDisableTiming);
    }
    if (!attr_done) {
        cudaFuncSetAttribute(k_s2h, cudaFuncAttributeMaxDynamicSharedMemorySize,
                             STG * STGB);
        attr_done = true;
    }

    cudaEventRecord(ev_fork, 0);
    cudaStreamWaitEvent(s_side, ev_fork, 0);

    // #1: fp32->fp16 conversion (main stream; GEMM depends on it)
    k_conv<<<(XN + WN) / 8 / 256, 256>>>(proj, Wk);
    // #2,#3 side
    k_init<<<16, 256, 0, s_side>>>();
    k_tg1<<<16, 256, 0, s_side>>>(text);
    // #4: GEMM (sampled by ncu)
    k_s2h<<<dim3(MROWS / BM, GY), 512, STG * STGB>>>();

    // side chain (overlaps GEMM)
    k_tg2<<<1, 1024, 0, s_side>>>();
    k_y<<<dim3(16, Lf), 256, 0, s_side>>>(proj);
    k_pres<<<128, 256, 0, s_side>>>(W1w, W1b);
    for (int l = 0; l < NSTEP; l++) {
        k_step_s<<<128, 256, 0, s_side>>>(W1w, l);
        k_step_c<<<512, 256, 0, s_side>>>(Wcw, Wcb, Wiw, Wib, Wfw, Wfb, bc, bi, bf);
    }
    k_qraw<<<512, 256, 0, s_side>>>(Wq);
    k_qln<<<1, 1024, 0, s_side>>>(lnw, lnb);
    k_av1<<<dim3(16, 8), 256, 0, s_side>>>(Wk);
    k_av2<<<16, 256, 0, s_side>>>();
    k_s13<<<MROWS / 8, 256, 0, s_side>>>(proj);

    cudaEventRecord(ev_join, s_side);
    cudaStreamWaitEvent(0, ev_join, 0);

    k_score<<<Lf, 192>>>();
    k_topk<<<Lf, 256>>>();
    k_select<<<1, 32>>>();
    k_gather<<<64, 256>>>(proj, out);
}

// round 13
// speedup vs baseline: 1.5836x; 1.5836x over previous
#include <cuda_runtime.h>
#include <cuda_fp16.h>
#include <cstdint>

#define Df 4096
#define Lf 24
#define Nf 576
#define Tf 128
#define REDf 1024
#define MROWS (Lf*Nf)
#define NSTEP 23
#define FOCUS 22
#define GY 16

#define BM 128
#define BN 256
#define NCH 128          // k-chunks of 32
#define STG 4
#define STGB 30720       // bytes per stage (A 10240 + B 20480)
#define XN (MROWS*Df)
#define WN (Df*Df)

// ---------------- device scratch ----------------
__device__ __half g_Xh[XN];
__device__ __half g_Wkh[WN];
__device__ float g_tgm[Df];
__device__ float g_tg[Df];
__device__ float g_y[Lf][Df];
__device__ float g_pres[NSTEP][REDf];
__device__ float g_c[Df];
__device__ float g_sc[Df];
__device__ float g_s[REDf];
__device__ float g_qraw[Df];
__device__ float g_wq[Df];
__device__ float g_Bs, g_Cs;
__device__ float g_ap[8][Df];
__device__ float g_vp[8][Df];
__device__ float g_a[Df];
__device__ float g_v[Df];
__device__ float g_S1[MROWS];
__device__ float g_S2part[GY][MROWS];
__device__ float g_S3[MROWS];
__device__ float g_zs[Lf][Nf];
__device__ float g_topv[Lf][64];
__device__ int   g_topi[Lf][64];
__device__ int   g_sel_li[64];
__device__ int   g_sel_idx[64];

// ---------------- helpers ----------------
__device__ __forceinline__ float warpsum(float v) {
    #pragma unroll
    for (int o = 16; o; o >>= 1) v += __shfl_xor_sync(0xffffffffu, v, o);
    return v;
}

__device__ __forceinline__ float blocksum(float v, float* red) {
    int tid = threadIdx.x, ln = tid & 31, w = tid >> 5, nw = blockDim.x >> 5;
    float s = warpsum(v);
    if (ln == 0) red[w] = s;
    __syncthreads();
    if (w == 0) {
        float r = (ln < nw) ? red[ln] : 0.f;
        r = warpsum(r);
        if (ln == 0) red[0] = r;
    }
    __syncthreads();
    float out = red[0];
    __syncthreads();
    return out;
}

__device__ __forceinline__ float sigm_(float x) { return 1.f / (1.f + expf(-x)); }

__device__ __forceinline__ uint32_t smem_u32(const void* p) {
    uint32_t a;
    asm("{ .reg .u64 t; cvta.to.shared.u64 t, %1; cvt.u32.u64 %0, t; }" : "=r"(a) : "l"(p));
    return a;
}

__device__ __forceinline__ void mma_f16(float c[4], uint32_t a0, uint32_t a1,
                                        uint32_t a2, uint32_t a3,
                                        uint32_t b0, uint32_t b1) {
    asm volatile(
        "mma.sync.aligned.m16n8k16.row.col.f32.f16.f16.f32 "
        "{%0,%1,%2,%3}, {%4,%5,%6,%7}, {%8,%9}, {%0,%1,%2,%3};\n"
        : "+f"(c[0]), "+f"(c[1]), "+f"(c[2]), "+f"(c[3])
        : "r"(a0), "r"(a1), "r"(a2), "r"(a3), "r"(b0), "r"(b1));
}

#define LDSM4(r0, r1, r2, r3, addr) \
    asm volatile("ldmatrix.sync.aligned.m8n8.x4.shared.b16 {%0,%1,%2,%3}, [%4];" \
                 : "=r"(r0), "=r"(r1), "=r"(r2), "=r"(r3) : "r"(addr))

#define CPA16(dst, src) \
    asm volatile("cp.async.cg.shared.global [%0], [%1], 16;" :: "r"(dst), "l"(src) : "memory")
#define CPA_COMMIT() asm volatile("cp.async.commit_group;" ::: "memory")
#define CPA_WAIT2()  asm volatile("cp.async.wait_group 2;" ::: "memory")

__device__ __forceinline__ uint32_t pack_h2(float lo, float hi) {
    __half2 h = __floats2half2_rn(lo, hi);
    return reinterpret_cast<uint32_t&>(h);
}

// ---------------- conversion (fp32 -> fp16), one pass ----------------
__global__ void k_conv(const float* __restrict__ X, const float* __restrict__ Wk) {
    size_t i = ((size_t)blockIdx.x * 256 + threadIdx.x) * 8;
    const float* src; __half* dst; size_t off;
    if (i < (size_t)XN) { src = X; dst = g_Xh; off = i; }
    else { src = Wk; dst = g_Wkh; off = i - (size_t)XN; }
    float4 a = *(const float4*)(src + off);
    float4 b = *(const float4*)(src + off + 4);
    uint4 o;
    o.x = pack_h2(a.x, a.y); o.y = pack_h2(a.z, a.w);
    o.z = pack_h2(b.x, b.y); o.w = pack_h2(b.z, b.w);
    *(uint4*)(dst + off) = o;
}

// ---------------- small kernels ----------------
__global__ void k_init() {
    int d = blockIdx.x * blockDim.x + threadIdx.x;
    if (d < Df) { g_c[d] = 0.f; g_sc[d] = 0.5f; }
}

__global__ void k_tg1(const float* __restrict__ text) {
    int d = blockIdx.x * blockDim.x + threadIdx.x;
    float s = 0.f;
    for (int t = 0; t < Tf; t++) s += text[(size_t)t * Df + d];
    g_tgm[d] = s * (1.0f / Tf);
}

__global__ void k_tg2() {
    __shared__ float red[32];
    int tid = threadIdx.x;
    float v[4];
    #pragma unroll
    for (int j = 0; j < 4; j++) v[j] = g_tgm[tid + j * 1024];
    float tot = blocksum(v[0] + v[1] + v[2] + v[3], red);
    float mu = tot * (1.f / Df);
    float q = 0.f;
    #pragma unroll
    for (int j = 0; j < 4; j++) { float dd = v[j] - mu; q += dd * dd; }
    float var = blocksum(q, red) * (1.f / Df);
    float inv = rsqrtf(var + 1e-5f);
    #pragma unroll
    for (int j = 0; j < 4; j++) g_tg[tid + j * 1024] = (v[j] - mu) * inv;
}

__global__ void k_y(const float* __restrict__ proj) {
    int l = blockIdx.y;
    int d = blockIdx.x * 256 + threadIdx.x;
    const float* p = proj + (size_t)l * Nf * Df + d;
    float s = 0.f;
    for (int n = 0; n < Nf; n++) s += p[(size_t)n * Df];
    g_y[l][d] = s * (1.0f / Nf);
}

__global__ void k_pres(const float* __restrict__ W1w, const float* __restrict__ W1b) {
    int warp = (blockIdx.x * blockDim.x + threadIdx.x) >> 5;
    int lane = threadIdx.x & 31;
    if (warp >= REDf) return;
    const float* rowY = W1w + (size_t)warp * (3 * Df) + Df;
    const float* rowT = rowY + Df;
    float accT = 0.f;
    float accL[NSTEP];
    #pragma unroll
    for (int l = 0; l < NSTEP; l++) accL[l] = 0.f;
    for (int d = lane; d < Df; d += 32) {
        float wy = rowY[d];
        float wt = rowT[d];
        accT += wt * g_tg[d];
        #pragma unroll
        for (int l = 0; l < NSTEP; l++) accL[l] += wy * g_y[l][d];
    }
    accT = warpsum(accT);
    #pragma unroll
    for (int l = 0; l < NSTEP; l++) accL[l] = warpsum(accL[l]);
    if (lane == 0) {
        float base = W1b[warp] + accT;
        #pragma unroll
        for (int l = 0; l < NSTEP; l++) g_pres[l][warp] = base + accL[l];
    }
}

// ------- fused S2 GEMM: 128x256 tile, 512 thr, acc 64/warp, 4-stage ----------
__global__ void __launch_bounds__(512, 1) k_s2h() {
    extern __shared__ __half sh[];
    uint32_t sbase = smem_u32(sh);
    int tid = threadIdx.x;
    int lane = tid & 31, warp = tid >> 5;
    int wm = warp >> 2, wn = warp & 3;   // 4 m-warps (32 rows) x 4 n-warps (64 cols)
    int g = lane >> 2;
    int row_block = blockIdx.x * BM;
    int e0 = blockIdx.y * BN;

    // ldmatrix per-lane addressing (proven mapping, unchanged from R11)
    int arow = lane & 15;
    int akoff = (lane >> 4) * 8;              // halves
    int brow = (lane & 7) + ((lane & 16) >> 1);
    int bkoff = (lane & 8) ? 8 : 0;           // halves

    float acc[2][8][4];
    #pragma unroll
    for (int mt = 0; mt < 2; mt++)
        #pragma unroll
        for (int ni = 0; ni < 8; ni++)
            #pragma unroll
            for (int r = 0; r < 4; r++) acc[mt][ni][r] = 0.f;

    // loader: A = 1 seg/thread (128 rows x 4 segs = 512), B = 2 segs (1024)
    int arow_ld = tid >> 2, aq_ld = tid & 3;

    auto issue = [&](int c) {
        int sl = c & (STG - 1);
        int kb = c * 32;                     // half offset within row
        {
            const __half* sa = g_Xh + (size_t)(row_block + arow_ld) * Df + kb + aq_ld * 8;
            uint32_t da = sbase + (uint32_t)(sl * STGB + arow_ld * 80 + aq_ld * 16);
            CPA16(da, sa);
        }
        #pragma unroll
        for (int i = 0; i < 2; i++) {
            int seg = tid * 2 + i;
            int row = seg >> 2, q = seg & 3;   // row 0..255
            const __half* sb = g_Wkh + (size_t)(e0 + row) * Df + kb + q * 8;
            uint32_t db = sbase + (uint32_t)(sl * STGB + 10240 + row * 80 + q * 16);
            CPA16(db, sb);
        }
    };

    issue(0); CPA_COMMIT();
    issue(1); CPA_COMMIT();
    issue(2); CPA_COMMIT();

    for (int c = 0; c < NCH; ++c) {
        CPA_WAIT2();                      // 3 pending -> oldest (chunk c) done
        __syncthreads();
        int sl = c & (STG - 1);
        uint32_t abase = sbase + sl * STGB;
        uint32_t bbase = abase + 10240;

        #pragma unroll
        for (int kk = 0; kk < 2; kk++) {
            uint32_t a0[4], a1[4];
            uint32_t aaddr = abase + (uint32_t)((wm * 32 + arow) * 80 + (kk * 16 + akoff) * 2);
            LDSM4(a0[0], a0[1], a0[2], a0[3], aaddr);
            LDSM4(a1[0], a1[1], a1[2], a1[3], aaddr + 16 * 80);
            #pragma unroll
            for (int p = 0; p < 4; p++) {
                uint32_t b[4];
                uint32_t baddr = bbase + (uint32_t)((wn * 64 + p * 16 + brow) * 80 + (kk * 16 + bkoff) * 2);
                LDSM4(b[0], b[1], b[2], b[3], baddr);
                mma_f16(acc[0][2 * p],     a0[0], a0[1], a0[2], a0[3], b[0], b[1]);
                mma_f16(acc[0][2 * p + 1], a0[0], a0[1], a0[2], a0[3], b[2], b[3]);
                mma_f16(acc[1][2 * p],     a1[0], a1[1], a1[2], a1[3], b[0], b[1]);
                mma_f16(acc[1][2 * p + 1], a1[0], a1[1], a1[2], a1[3], b[2], b[3]);
            }
        }

        if (c + 3 < NCH) issue(c + 3);
        CPA_COMMIT();
    }

    // squares + reductions
    float s2p[4];
    #pragma unroll
    for (int mt = 0; mt < 2; mt++) {
        float p0 = 0.f, p1 = 0.f;
        #pragma unroll
        for (int ni = 0; ni < 8; ni++) {
            p0 += acc[mt][ni][0] * acc[mt][ni][0] + acc[mt][ni][1] * acc[mt][ni][1];
            p1 += acc[mt][ni][2] * acc[mt][ni][2] + acc[mt][ni][3] * acc[mt][ni][3];
        }
        s2p[mt * 2 + 0] = p0;   // row wm*32 + mt*16 + g
        s2p[mt * 2 + 1] = p1;   // row wm*32 + mt*16 + g + 8
    }
    #pragma unroll
    for (int j = 0; j < 4; j++) {
        s2p[j] += __shfl_xor_sync(0xffffffffu, s2p[j], 1);
        s2p[j] += __shfl_xor_sync(0xffffffffu, s2p[j], 2);
    }
    __syncthreads();                       // stage smem reads done; reuse
    float* s2sh = (float*)sh;              // [4 nwarps][128 rows]
    if ((lane & 3) == 0) {
        s2sh[wn * BM + wm * 32 + g]      = s2p[0];
        s2sh[wn * BM + wm * 32 + g + 8]  = s2p[1];
        s2sh[wn * BM + wm * 32 + g + 16] = s2p[2];
        s2sh[wn * BM + wm * 32 + g + 24] = s2p[3];
    }
    __syncthreads();
    if (tid < BM) {
        float s = s2sh[tid] + s2sh[BM + tid] + s2sh[2 * BM + tid] + s2sh[3 * BM + tid];
        g_S2part[blockIdx.y][row_block + tid] = s;
    }
}

// ---------------- DSU / q pipeline ----------------
__global__ void k_step_s(const float* __restrict__ W1w, int l) {
    int warp = (blockIdx.x * 256 + threadIdx.x) >> 5;
    int lane = threadIdx.x & 31;
    const float4* row = (const float4*)(W1w + (size_t)warp * (3 * Df));
    const float4* scv = (const float4*)g_sc;
    float acc = 0.f;
    for (int i = lane; i < Df / 4; i += 32) {
        float4 w = row[i]; float4 s = scv[i];
        acc += w.x * s.x + w.y * s.y + w.z * s.z + w.w * s.w;
    }
    acc = warpsum(acc);
    if (lane == 0) {
        float v = g_pres[l][warp] + acc;
        g_s[warp] = v > 0.f ? v : 0.f;
    }
}

__global__ void k_step_c(const float* __restrict__ Wc, const float* __restrict__ Wcb,
                         const float* __restrict__ Wi, const float* __restrict__ Wib,
                         const float* __restrict__ Wf, const float* __restrict__ Wfb,
                         const float* __restrict__ bc, const float* __restrict__ bi,
                         const float* __restrict__ bf) {
    int d = (blockIdx.x * 256 + threadIdx.x) >> 5;
    int lane = threadIdx.x & 31;
    const float4* rc = (const float4*)(Wc + (size_t)d * REDf);
    const float4* ri = (const float4*)(Wi + (size_t)d * REDf);
    const float4* rf = (const float4*)(Wf + (size_t)d * REDf);
    const float4* sv = (const float4*)g_s;
    float ac = 0.f, ai = 0.f, af = 0.f;
    for (int i = lane; i < REDf / 4; i += 32) {
        float4 s = sv[i];
        float4 c4 = rc[i]; ac += c4.x * s.x + c4.y * s.y + c4.z * s.z + c4.w * s.w;
        float4 i4 = ri[i]; ai += i4.x * s.x + i4.y * s.y + i4.z * s.z + i4.w * s.w;
        float4 f4 = rf[i]; af += f4.x * s.x + f4.y * s.y + f4.z * s.z + f4.w * s.w;
    }
    ac = warpsum(ac); ai = warpsum(ai); af = warpsum(af);
    if (lane == 0) {
        float ct = tanhf(ac + Wcb[d] + bc[d]);
        float iv = sigm_(ai + Wib[d] + bi[d]);
        float fv = sigm_(af + Wfb[d] + bf[d]);
        float cn = fv * g_c[d] + iv * ct;
        g_c[d] = cn;
        g_sc[d] = sigm_(cn);
    }
}

__global__ void k_qraw(const float* __restrict__ Wq) {
    int e = (blockIdx.x * 256 + threadIdx.x) >> 5;
    int lane = threadIdx.x & 31;
    const float4* row = (const float4*)(Wq + (size_t)e * Df);
    const float4* cv = (const float4*)g_c;
    float acc = 0.f;
    for (int i = lane; i < Df / 4; i += 32) {
        float4 w = row[i]; float4 c4 = cv[i];
        acc += w.x * c4.x + w.y * c4.y + w.z * c4.z + w.w * c4.w;
    }
    acc = warpsum(acc);
    if (lane == 0) g_qraw[e] = acc;
}

__global__ void k_qln(const float* __restrict__ lnw, const float* __restrict__ lnb) {
    __shared__ float red[32];
    int tid = threadIdx.x;
    float v[4];
    #pragma unroll
    for (int j = 0; j < 4; j++) v[j] = g_qraw[tid + j * 1024];
    float tot = blocksum(v[0] + v[1] + v[2] + v[3], red);
    float mu = tot * (1.f / Df);
    float q = 0.f;
    #pragma unroll
    for (int j = 0; j < 4; j++) { float dd = v[j] - mu; q += dd * dd; }
    float var = blocksum(q, red) * (1.f / Df);
    float inv = rsqrtf(var + 1e-5f);
    float Bp = 0.f, Cp = 0.f;
    #pragma unroll
    for (int j = 0; j < 4; j++) {
        int e = tid + j * 1024;
        float w = lnw[e], b = lnb[e];
        float qv = (v[j] - mu) * inv * w + b;
        float wq = w * qv;
        g_wq[e] = wq;
        Bp += wq;
        Cp += b * qv;
    }
    float Bt = blocksum(Bp, red);
    float Ct = blocksum(Cp, red);
    if (tid == 0) { g_Bs = Bt; g_Cs = Ct; }
}

__global__ void k_av1(const float* __restrict__ Wk) {
    int d = blockIdx.x * 256 + threadIdx.x;
    int ep = blockIdx.y;
    float sa = 0.f, sv = 0.f;
    int e0 = ep * (Df / 8);
    for (int e = e0; e < e0 + Df / 8; e++) {
        float wk = __ldg(Wk + (size_t)e * Df + d);
        sa += wk;
        sv += g_wq[e] * wk;
    }
    g_ap[ep][d] = sa;
    g_vp[ep][d] = sv;
}

__global__ void k_av2() {
    int d = blockIdx.x * 256 + threadIdx.x;
    float sa = 0.f, sv = 0.f;
    #pragma unroll
    for (int p = 0; p < 8; p++) { sa += g_ap[p][d]; sv += g_vp[p][d]; }
    g_a[d] = sa;
    g_v[d] = sv;
}

__global__ void k_s13(const float* __restrict__ proj) {
    int row = (blockIdx.x * 256 + threadIdx.x) >> 5;
    int lane = threadIdx.x & 31;
    const float4* x = (const float4*)(proj + (size_t)row * Df);
    const float4* av = (const float4*)g_a;
    const float4* vv = (const float4*)g_v;
    float s1 = 0.f, s3 = 0.f;
    for (int i = lane; i < Df / 4; i += 32) {
        float4 xx = x[i];
        float4 aa = av[i];
        float4 v4 = vv[i];
        s1 += xx.x * aa.x + xx.y * aa.y + xx.z * aa.z + xx.w * aa.w;
        s3 += xx.x * v4.x + xx.y * v4.y + xx.z * v4.z + xx.w * v4.w;
    }
    s1 = warpsum(s1); s3 = warpsum(s3);
    if (lane == 0) { g_S1[row] = s1; g_S3[row] = s3; }
}

// ---------------- scores, z, topk, select, gather ----------------
__global__ void k_score() {
    int l = blockIdx.x;
    __shared__ float sc[Nf];
    __shared__ float red[32];
    int tid = threadIdx.x;
    float B = g_Bs, C = g_Cs;
    float part = 0.f;
    float loc[3];
    #pragma unroll
    for (int j = 0; j < 3; j++) {
        int n = tid + j * 192;
        int i = l * Nf + n;
        float s2 = 0.f;
        #pragma unroll
        for (int p = 0; p < GY; p++) s2 += g_S2part[p][i];
        float mu = g_S1[i] * (1.f / Df);
        float var = s2 * (1.f / Df) - mu * mu;
        float s = (g_S3[i] - mu * B) / sqrtf(var + 1e-5f) + C;
        sc[n] = s;
        loc[j] = s;
        part += s;
    }
    float mu_s = blocksum(part, red) * (1.f / Nf);
    float q = 0.f;
    #pragma unroll
    for (int j = 0; j < 3; j++) { float dd = loc[j] - mu_s; q += dd * dd; }
    float sd = sqrtf(blocksum(q, red) * (1.f / Nf));
    float inv = 1.f / (sd + 1e-6f);
    #pragma unroll
    for (int j = 0; j < 3; j++) {
        int n = tid + j * 192;
        g_zs[l][n] = (sc[n] - mu_s) * inv;
    }
}

__global__ void k_topk() {
    int l = blockIdx.x;
    __shared__ float sv[Nf];
    __shared__ float bv[8];
    __shared__ int bidx[8];
    int tid = threadIdx.x;
    int warp = tid >> 5, lane = tid & 31;
    for (int n = tid; n < Nf; n += 256) sv[n] = g_zs[l][n];
    __syncthreads();
    for (int t = 0; t < 64; t++) {
        float best = -3.4e38f;
        int besti = Nf;
        for (int n = tid; n < Nf; n += 256) {
            float v = sv[n];
            if (v > best || (v == best && n < besti)) { best = v; besti = n; }
        }
        #pragma unroll
        for (int o = 16; o; o >>= 1) {
            float ov = __shfl_xor_sync(0xffffffffu, best, o);
            int oi = __shfl_xor_sync(0xffffffffu, besti, o);
            if (ov > best || (ov == best && oi < besti)) { best = ov; besti = oi; }
        }
        if (lane == 0) { bv[warp] = best; bidx[warp] = besti; }
        __syncthreads();
        if (tid == 0) {
            float fb = bv[0]; int fi = bidx[0];
            #pragma unroll
            for (int w = 1; w < 8; w++)
                if (bv[w] > fb || (bv[w] == fb && bidx[w] < fi)) { fb = bv[w]; fi = bidx[w]; }
            g_topv[l][t] = fb;
            g_topi[l][t] = fi;
            sv[fi] = -3.4e38f;
        }
        __syncthreads();
    }
}

__global__ void k_select() {
    if (threadIdx.x != 0 || blockIdx.x != 0) return;
    float conf[Lf];
    for (int l = 0; l < Lf; l++) conf[l] = g_topv[l][0];

    int kper[Lf];
    for (int l = 0; l < Lf; l++) kper[l] = 0;
    kper[FOCUS] = 64;
    int rest = 64;

    int other[Lf]; int no = 0;
    for (int l = 0; l < Lf; l++)
        if (l != FOCUS && conf[l] > 2.0f) other[no++] = l;

    if (no > 0 && rest > 0) {
        float w[Lf];
        float mx = -3.4e38f;
        for (int j = 0; j < no; j++) if (conf[other[j]] > mx) mx = conf[other[j]];
        float sum = 0.f;
        for (int j = 0; j < no; j++) { w[j] = expf(conf[other[j]] - mx); sum += w[j]; }
        for (int j = 0; j < no; j++) w[j] /= sum;
        long long alloc[Lf]; long long asum = 0;
        for (int j = 0; j < no; j++) { alloc[j] = (long long)floorf(w[j] * (float)rest); asum += alloc[j]; }
        long long rem = rest - asum;
        bool used[Lf];
        for (int j = 0; j < no; j++) used[j] = false;
        for (int t = 0; t < no && rem > 0; t++) {
            int best = -1;
            for (int j = 0; j < no; j++)
                if (!used[j] && (best < 0 || w[j] > w[best])) best = j;
            used[best] = true;
            alloc[best]++; rem--;
        }
        for (int j = 0; j < no; j++)
            if (alloc[j] > 0) {
                int v = (int)alloc[j];
                kper[other[j]] = v < Nf ? v : Nf;
            }
    }

    float sc[192]; int fli[192], fidx[192]; int M = 0;
    for (int l = 0; l < Lf; l++) {
        int kl = kper[l];
        for (int t = 0; t < kl; t++) {
            fli[M] = l; fidx[M] = g_topi[l][t]; sc[M] = g_topv[l][t]; M++;
        }
    }

    int final_k = M < 64 ? M : 64;
    int focus_min = final_k < 32 ? final_k : 32;

    int sel[64]; int ns = 0;
    bool taken[192];
    for (int m = 0; m < M; m++) taken[m] = false;

    for (int t = 0; t < focus_min; t++) {
        int best = -1;
        for (int m = 0; m < M; m++)
            if (fli[m] == FOCUS && !taken[m] && (best < 0 || sc[m] > sc[best])) best = m;
        if (best < 0) break;
        taken[best] = true; sel[ns++] = best;
    }
    int remain = final_k - ns;
    for (int t = 0; t < remain; t++) {
        int best = -1;
        for (int m = 0; m < M; m++)
            if (!taken[m] && (best < 0 || sc[m] > sc[best])) best = m;
        if (best < 0) break;
        taken[best] = true; sel[ns++] = best;
    }
    for (int i = 0; i < ns; i++) {
        int bj = i;
        for (int j = i + 1; j < ns; j++)
            if (sc[sel[j]] > sc[sel[bj]]) bj = j;
        int tmp = sel[i]; sel[i] = sel[bj]; sel[bj] = tmp;
    }
    for (int i = 0; i < ns; i++) {
        g_sel_li[i] = fli[sel[i]];
        g_sel_idx[i] = fidx[sel[i]];
    }
}

__global__ void k_gather(const float* __restrict__ proj, float* __restrict__ out) {
    int j = blockIdx.x;
    int li = g_sel_li[j], idx = g_sel_idx[j];
    const float4* src = (const float4*)(proj + ((size_t)li * Nf + idx) * Df);
    float4* dst = (float4*)(out + (size_t)j * Df);
    for (int i = threadIdx.x; i < Df / 4; i += blockDim.x) dst[i] = src[i];
}

// ---------------- launch ----------------
extern "C" void kernel_launch(void* const* d_in, const int* in_sizes, int n_in,
                              void* d_out, int out_size) {
    const float* text = (const float*)d_in[0];
    const float* proj = (const float*)d_in[1];
    const float* Wq   = (const float*)d_in[2];
    const float* Wk   = (const float*)d_in[3];
    const float* lnw  = (const float*)d_in[4];
    const float* lnb  = (const float*)d_in[5];
    const float* W1w  = (const float*)d_in[6];
    const float* W1b  = (const float*)d_in[7];
    const float* Wcw  = (const float*)d_in[8];
    const float* Wcb  = (const float*)d_in[9];
    const float* Wiw  = (const float*)d_in[10];
    const float* Wib  = (const float*)d_in[11];
    const float* Wfw  = (const float*)d_in[12];
    const float* Wfb  = (const float*)d_in[13];
    const float* bc   = (const float*)d_in[14];
    const float* bi   = (const float*)d_in[15];
    const float* bf   = (const float*)d_in[16];
    float* out = (float*)d_out;

    static cudaStream_t s_side = nullptr;
    static cudaEvent_t ev_fork = nullptr, ev_join = nullptr;
    static bool attr_done = false;
    if (s_side == nullptr) {
        cudaStreamCreateWithFlags(&s_side, cudaStreamNonBlocking);
        cudaEventCreateWithFlags(&ev_fork, cudaEventDisableTiming);
        cudaEventCreateWithFlags(&ev_join, cudaEventDisableTiming);
    }
    if (!attr_done) {
        cudaFuncSetAttribute(k_s2h, cudaFuncAttributeMaxDynamicSharedMemorySize,
                             STG * STGB);
        attr_done = true;
    }

    cudaEventRecord(ev_fork, 0);
    cudaStreamWaitEvent(s_side, ev_fork, 0);

    // #1: fp32->fp16 conversion (main stream; GEMM depends on it)
    k_conv<<<(XN + WN) / 8 / 256, 256>>>(proj, Wk);
    // #2,#3 side
    k_init<<<16, 256, 0, s_side>>>();
    k_tg1<<<16, 256, 0, s_side>>>(text);
    // #4: GEMM (sampled by ncu)
    k_s2h<<<dim3(MROWS / BM, GY), 512, STG * STGB>>>();

    // side chain (overlaps GEMM)
    k_tg2<<<1, 1024, 0, s_side>>>();
    k_y<<<dim3(16, Lf), 256, 0, s_side>>>(proj);
    k_pres<<<128, 256, 0, s_side>>>(W1w, W1b);
    for (int l = 0; l < NSTEP; l++) {
        k_step_s<<<128, 256, 0, s_side>>>(W1w, l);
        k_step_c<<<512, 256, 0, s_side>>>(Wcw, Wcb, Wiw, Wib, Wfw, Wfb, bc, bi, bf);
    }
    k_qraw<<<512, 256, 0, s_side>>>(Wq);
    k_qln<<<1, 1024, 0, s_side>>>(lnw, lnb);
    k_av1<<<dim3(16, 8), 256, 0, s_side>>>(Wk);
    k_av2<<<16, 256, 0, s_side>>>();
    k_s13<<<MROWS / 8, 256, 0, s_side>>>(proj);

    cudaEventRecord(ev_join, s_side);
    cudaStreamWaitEvent(0, ev_join, 0);

    k_score<<<Lf, 192>>>();
    k_topk<<<Lf, 256>>>();
    k_select<<<1, 32>>>();
    k_gather<<<64, 256>>>(proj, out);
}

// round 15
// speedup vs baseline: 1.6330x; 1.0312x over previous
#include <cuda_runtime.h>
#include <cuda_fp16.h>
#include <cstdint>

#define Df 4096
#define Lf 24
#define Nf 576
#define Tf 128
#define REDf 1024
#define MROWS (Lf*Nf)
#define NSTEP 23
#define FOCUS 22
#define GY 16

#define BM 128
#define BN 256
#define NCH 128
#define STG 4
#define STGB 30720
#define XN (MROWS*Df)
#define WN (Df*Df)
#define A1 (REDf*Df)
#define A2 (Df*REDf)

// ---------------- device scratch ----------------
__device__ __half g_Xh[XN];
__device__ __half g_Wkh[WN];
__device__ __half g_W1h[REDf*Df];
__device__ __half g_Wch[Df*REDf];
__device__ __half g_Wih[Df*REDf];
__device__ __half g_Wfh[Df*REDf];
__device__ float g_tgm[Df];
__device__ float g_tg[Df];
__device__ float g_y[Lf][Df];
__device__ float g_pres[NSTEP][REDf];
__device__ float g_c[Df];
__device__ float g_sc[Df];
__device__ float g_s[REDf];
__device__ float g_qraw[Df];
__device__ float g_wq[Df];
__device__ float g_Bs, g_Cs;
__device__ float g_ap[8][Df];
__device__ float g_vp[8][Df];
__device__ float g_a[Df];
__device__ float g_v[Df];
__device__ float g_S1[MROWS];
__device__ float g_S2part[GY][MROWS];
__device__ float g_S3[MROWS];
__device__ float g_zs[Lf][Nf];
__device__ float g_topv[Lf][64];
__device__ int   g_topi[Lf][64];
__device__ int   g_sel_li[64];
__device__ int   g_sel_idx[64];

// ---------------- helpers ----------------
__device__ __forceinline__ float warpsum(float v) {
    #pragma unroll
    for (int o = 16; o; o >>= 1) v += __shfl_xor_sync(0xffffffffu, v, o);
    return v;
}

__device__ __forceinline__ float blocksum(float v, float* red) {
    int tid = threadIdx.x, ln = tid & 31, w = tid >> 5, nw = blockDim.x >> 5;
    float s = warpsum(v);
    if (ln == 0) red[w] = s;
    __syncthreads();
    if (w == 0) {
        float r = (ln < nw) ? red[ln] : 0.f;
        r = warpsum(r);
        if (ln == 0) red[0] = r;
    }
    __syncthreads();
    float out = red[0];
    __syncthreads();
    return out;
}

__device__ __forceinline__ float sigm_(float x) { return 1.f / (1.f + expf(-x)); }

__device__ __forceinline__ uint32_t smem_u32(const void* p) {
    uint32_t a;
    asm("{ .reg .u64 t; cvta.to.shared.u64 t, %1; cvt.u32.u64 %0, t; }" : "=r"(a) : "l"(p));
    return a;
}

__device__ __forceinline__ void mma_f16(float c[4], uint32_t a0, uint32_t a1,
                                        uint32_t a2, uint32_t a3,
                                        uint32_t b0, uint32_t b1) {
    asm volatile(
        "mma.sync.aligned.m16n8k16.row.col.f32.f16.f16.f32 "
        "{%0,%1,%2,%3}, {%4,%5,%6,%7}, {%8,%9}, {%0,%1,%2,%3};\n"
        : "+f"(c[0]), "+f"(c[1]), "+f"(c[2]), "+f"(c[3])
        : "r"(a0), "r"(a1), "r"(a2), "r"(a3), "r"(b0), "r"(b1));
}

#define LDSM4(r0, r1, r2, r3, addr) \
    asm volatile("ldmatrix.sync.aligned.m8n8.x4.shared.b16 {%0,%1,%2,%3}, [%4];" \
                 : "=r"(r0), "=r"(r1), "=r"(r2), "=r"(r3) : "r"(addr))

#define CPA16(dst, src) \
    asm volatile("cp.async.cg.shared.global [%0], [%1], 16;" :: "r"(dst), "l"(src) : "memory")
#define CPA_COMMIT() asm volatile("cp.async.commit_group;" ::: "memory")
#define CPA_WAIT2()  asm volatile("cp.async.wait_group 2;" ::: "memory")

__device__ __forceinline__ uint32_t pack_h2(float lo, float hi) {
    __half2 h = __floats2half2_rn(lo, hi);
    return reinterpret_cast<uint32_t&>(h);
}

__device__ __forceinline__ float2 h2f(uint32_t u) {
    __half2 h = *reinterpret_cast<__half2*>(&u);
    return __half22float2(h);
}

// ---------------- conversions ----------------
__global__ void k_conv(const float* __restrict__ X, const float* __restrict__ Wk) {
    size_t i = ((size_t)blockIdx.x * 256 + threadIdx.x) * 8;
    const float* src; __half* dst; size_t off;
    if (i < (size_t)XN) { src = X; dst = g_Xh; off = i; }
    else { src = Wk; dst = g_Wkh; off = i - (size_t)XN; }
    float4 a = *(const float4*)(src + off);
    float4 b = *(const float4*)(src + off + 4);
    uint4 o;
    o.x = pack_h2(a.x, a.y); o.y = pack_h2(a.z, a.w);
    o.z = pack_h2(b.x, b.y); o.w = pack_h2(b.z, b.w);
    *(uint4*)(dst + off) = o;
}

__global__ void k_conv2(const float* __restrict__ W1w, const float* __restrict__ Wc,
                        const float* __restrict__ Wi, const float* __restrict__ Wf) {
    size_t j = ((size_t)blockIdx.x * 256 + threadIdx.x) * 8;
    const float* src; __half* dst;
    if (j < (size_t)A1) {
        size_t r = j / Df, dcol = j - r * Df;
        src = W1w + r * (3 * (size_t)Df) + dcol;
        dst = g_W1h + j;
    } else if (j < (size_t)A1 + A2) { size_t o = j - A1; src = Wc + o; dst = g_Wch + o; }
    else if (j < (size_t)A1 + 2 * A2) { size_t o = j - A1 - A2; src = Wi + o; dst = g_Wih + o; }
    else { size_t o = j - A1 - 2 * (size_t)A2; src = Wf + o; dst = g_Wfh + o; }
    float4 a = *(const float4*)src;
    float4 b = *(const float4*)(src + 4);
    uint4 o;
    o.x = pack_h2(a.x, a.y); o.y = pack_h2(a.z, a.w);
    o.z = pack_h2(b.x, b.y); o.w = pack_h2(b.z, b.w);
    *(uint4*)dst = o;
}

// ---------------- small kernels ----------------
__global__ void k_init() {
    int d = blockIdx.x * blockDim.x + threadIdx.x;
    if (d < Df) { g_c[d] = 0.f; g_sc[d] = 0.5f; }
}

__global__ void k_tg1(const float* __restrict__ text) {
    int d = blockIdx.x * blockDim.x + threadIdx.x;
    float s = 0.f;
    for (int t = 0; t < Tf; t++) s += text[(size_t)t * Df + d];
    g_tgm[d] = s * (1.0f / Tf);
}

__global__ void k_tg2() {
    __shared__ float red[32];
    int tid = threadIdx.x;
    float v[4];
    #pragma unroll
    for (int j = 0; j < 4; j++) v[j] = g_tgm[tid + j * 1024];
    float tot = blocksum(v[0] + v[1] + v[2] + v[3], red);
    float mu = tot * (1.f / Df);
    float q = 0.f;
    #pragma unroll
    for (int j = 0; j < 4; j++) { float dd = v[j] - mu; q += dd * dd; }
    float var = blocksum(q, red) * (1.f / Df);
    float inv = rsqrtf(var + 1e-5f);
    #pragma unroll
    for (int j = 0; j < 4; j++) g_tg[tid + j * 1024] = (v[j] - mu) * inv;
}

__global__ void k_y_h() {
    int l = blockIdx.y;
    int dp = blockIdx.x * 256 + threadIdx.x;   // half2 pair idx (0..2047)
    const __half2* p = (const __half2*)(g_Xh + (size_t)l * Nf * Df) + dp;
    float sx = 0.f, sy = 0.f;
    for (int n = 0; n < Nf; n++) {
        float2 v = __half22float2(p[(size_t)n * (Df / 2)]);
        sx += v.x; sy += v.y;
    }
    g_y[l][2 * dp] = sx * (1.0f / Nf);
    g_y[l][2 * dp + 1] = sy * (1.0f / Nf);
}

__global__ void k_pres(const float* __restrict__ W1w, const float* __restrict__ W1b) {
    int warp = (blockIdx.x * blockDim.x + threadIdx.x) >> 5;
    int lane = threadIdx.x & 31;
    if (warp >= REDf) return;
    const float* rowY = W1w + (size_t)warp * (3 * Df) + Df;
    const float* rowT = rowY + Df;
    float accT = 0.f;
    float accL[NSTEP];
    #pragma unroll
    for (int l = 0; l < NSTEP; l++) accL[l] = 0.f;
    for (int d = lane; d < Df; d += 32) {
        float wy = rowY[d];
        float wt = rowT[d];
        accT += wt * g_tg[d];
        #pragma unroll
        for (int l = 0; l < NSTEP; l++) accL[l] += wy * g_y[l][d];
    }
    accT = warpsum(accT);
    #pragma unroll
    for (int l = 0; l < NSTEP; l++) accL[l] = warpsum(accL[l]);
    if (lane == 0) {
        float base = W1b[warp] + accT;
        #pragma unroll
        for (int l = 0; l < NSTEP; l++) g_pres[l][warp] = base + accL[l];
    }
}

// ------- fused S2 GEMM: 128x256 tile, 512 thr, acc 64/warp, 4-stage ----------
__global__ void __launch_bounds__(512, 1) k_s2h() {
    extern __shared__ __half sh[];
    uint32_t sbase = smem_u32(sh);
    int tid = threadIdx.x;
    int lane = tid & 31, warp = tid >> 5;
    int wm = warp >> 2, wn = warp & 3;
    int g = lane >> 2;
    int row_block = blockIdx.x * BM;
    int e0 = blockIdx.y * BN;

    int arow = lane & 15;
    int akoff = (lane >> 4) * 8;
    int brow = (lane & 7) + ((lane & 16) >> 1);
    int bkoff = (lane & 8) ? 8 : 0;

    float acc[2][8][4];
    #pragma unroll
    for (int mt = 0; mt < 2; mt++)
        #pragma unroll
        for (int ni = 0; ni < 8; ni++)
            #pragma unroll
            for (int r = 0; r < 4; r++) acc[mt][ni][r] = 0.f;

    int arow_ld = tid >> 2, aq_ld = tid & 3;

    auto issue = [&](int c) {
        int sl = c & (STG - 1);
        int kb = c * 32;
        {
            const __half* sa = g_Xh + (size_t)(row_block + arow_ld) * Df + kb + aq_ld * 8;
            uint32_t da = sbase + (uint32_t)(sl * STGB + arow_ld * 80 + aq_ld * 16);
            CPA16(da, sa);
        }
        #pragma unroll
        for (int i = 0; i < 2; i++) {
            int seg = tid * 2 + i;
            int row = seg >> 2, q = seg & 3;
            const __half* sb = g_Wkh + (size_t)(e0 + row) * Df + kb + q * 8;
            uint32_t db = sbase + (uint32_t)(sl * STGB + 10240 + row * 80 + q * 16);
            CPA16(db, sb);
        }
    };

    issue(0); CPA_COMMIT();
    issue(1); CPA_COMMIT();
    issue(2); CPA_COMMIT();

    for (int c = 0; c < NCH; ++c) {
        CPA_WAIT2();
        __syncthreads();
        int sl = c & (STG - 1);
        uint32_t abase = sbase + sl * STGB;
        uint32_t bbase = abase + 10240;

        #pragma unroll
        for (int kk = 0; kk < 2; kk++) {
            uint32_t a0[4], a1[4];
            uint32_t aaddr = abase + (uint32_t)((wm * 32 + arow) * 80 + (kk * 16 + akoff) * 2);
            LDSM4(a0[0], a0[1], a0[2], a0[3], aaddr);
            LDSM4(a1[0], a1[1], a1[2], a1[3], aaddr + 16 * 80);
            #pragma unroll
            for (int p = 0; p < 4; p++) {
                uint32_t b[4];
                uint32_t baddr = bbase + (uint32_t)((wn * 64 + p * 16 + brow) * 80 + (kk * 16 + bkoff) * 2);
                LDSM4(b[0], b[1], b[2], b[3], baddr);
                mma_f16(acc[0][2 * p],     a0[0], a0[1], a0[2], a0[3], b[0], b[1]);
                mma_f16(acc[0][2 * p + 1], a0[0], a0[1], a0[2], a0[3], b[2], b[3]);
                mma_f16(acc[1][2 * p],     a1[0], a1[1], a1[2], a1[3], b[0], b[1]);
                mma_f16(acc[1][2 * p + 1], a1[0], a1[1], a1[2], a1[3], b[2], b[3]);
            }
        }

        if (c + 3 < NCH) issue(c + 3);
        CPA_COMMIT();
    }

    float s2p[4];
    #pragma unroll
    for (int mt = 0; mt < 2; mt++) {
        float p0 = 0.f, p1 = 0.f;
        #pragma unroll
        for (int ni = 0; ni < 8; ni++) {
            p0 += acc[mt][ni][0] * acc[mt][ni][0] + acc[mt][ni][1] * acc[mt][ni][1];
            p1 += acc[mt][ni][2] * acc[mt][ni][2] + acc[mt][ni][3] * acc[mt][ni][3];
        }
        s2p[mt * 2 + 0] = p0;
        s2p[mt * 2 + 1] = p1;
    }
    #pragma unroll
    for (int j = 0; j < 4; j++) {
        s2p[j] += __shfl_xor_sync(0xffffffffu, s2p[j], 1);
        s2p[j] += __shfl_xor_sync(0xffffffffu, s2p[j], 2);
    }
    __syncthreads();
    float* s2sh = (float*)sh;
    if ((lane & 3) == 0) {
        s2sh[wn * BM + wm * 32 + g]      = s2p[0];
        s2sh[wn * BM + wm * 32 + g + 8]  = s2p[1];
        s2sh[wn * BM + wm * 32 + g + 16] = s2p[2];
        s2sh[wn * BM + wm * 32 + g + 24] = s2p[3];
    }
    __syncthreads();
    if (tid < BM) {
        float s = s2sh[tid] + s2sh[BM + tid] + s2sh[2 * BM + tid] + s2sh[3 * BM + tid];
        g_S2part[blockIdx.y][row_block + tid] = s;
    }
}

// ---------------- DSU / q pipeline (fp16 weights) ----------------
__global__ void k_step_s(int l) {
    int warp = (blockIdx.x * 256 + threadIdx.x) >> 5;
    int lane = threadIdx.x & 31;
    const uint4* row = (const uint4*)(g_W1h + (size_t)warp * Df);
    const float4* scv = (const float4*)g_sc;
    float acc = 0.f;
    for (int i = lane; i < Df / 8; i += 32) {
        uint4 w = row[i];
        float4 s0 = scv[2 * i], s1 = scv[2 * i + 1];
        float2 f0 = h2f(w.x), f1 = h2f(w.y), f2 = h2f(w.z), f3 = h2f(w.w);
        acc += f0.x * s0.x + f0.y * s0.y + f1.x * s0.z + f1.y * s0.w
             + f2.x * s1.x + f2.y * s1.y + f3.x * s1.z + f3.y * s1.w;
    }
    acc = warpsum(acc);
    if (lane == 0) {
        float v = g_pres[l][warp] + acc;
        g_s[warp] = v > 0.f ? v : 0.f;
    }
}

__global__ void k_step_c(const float* __restrict__ Wcb, const float* __restrict__ Wib,
                         const float* __restrict__ Wfb,
                         const float* __restrict__ bc, const float* __restrict__ bi,
                         const float* __restrict__ bf) {
    int d = (blockIdx.x * 256 + threadIdx.x) >> 5;
    int lane = threadIdx.x & 31;
    const uint4* rc = (const uint4*)(g_Wch + (size_t)d * REDf);
    const uint4* ri = (const uint4*)(g_Wih + (size_t)d * REDf);
    const uint4* rf = (const uint4*)(g_Wfh + (size_t)d * REDf);
    const float4* sv = (const float4*)g_s;
    float ac = 0.f, ai = 0.f, af = 0.f;
    for (int i = lane; i < REDf / 8; i += 32) {
        float4 s0 = sv[2 * i], s1 = sv[2 * i + 1];
        uint4 c8 = rc[i];
        {
            float2 f0 = h2f(c8.x), f1 = h2f(c8.y), f2 = h2f(c8.z), f3 = h2f(c8.w);
            ac += f0.x * s0.x + f0.y * s0.y + f1.x * s0.z + f1.y * s0.w
                + f2.x * s1.x + f2.y * s1.y + f3.x * s1.z + f3.y * s1.w;
        }
        uint4 i8 = ri[i];
        {
            float2 f0 = h2f(i8.x), f1 = h2f(i8.y), f2 = h2f(i8.z), f3 = h2f(i8.w);
            ai += f0.x * s0.x + f0.y * s0.y + f1.x * s0.z + f1.y * s0.w
                + f2.x * s1.x + f2.y * s1.y + f3.x * s1.z + f3.y * s1.w;
        }
        uint4 f8 = rf[i];
        {
            float2 f0 = h2f(f8.x), f1 = h2f(f8.y), f2 = h2f(f8.z), f3 = h2f(f8.w);
            af += f0.x * s0.x + f0.y * s0.y + f1.x * s0.z + f1.y * s0.w
                + f2.x * s1.x + f2.y * s1.y + f3.x * s1.z + f3.y * s1.w;
        }
    }
    ac = warpsum(ac); ai = warpsum(ai); af = warpsum(af);
    if (lane == 0) {
        float ct = tanhf(ac + Wcb[d] + bc[d]);
        float iv = sigm_(ai + Wib[d] + bi[d]);
        float fv = sigm_(af + Wfb[d] + bf[d]);
        float cn = fv * g_c[d] + iv * ct;
        g_c[d] = cn;
        g_sc[d] = sigm_(cn);
    }
}

__global__ void k_qraw(const float* __restrict__ Wq) {
    int e = (blockIdx.x * 256 + threadIdx.x) >> 5;
    int lane = threadIdx.x & 31;
    const float4* row = (const float4*)(Wq + (size_t)e * Df);
    const float4* cv = (const float4*)g_c;
    float acc = 0.f;
    for (int i = lane; i < Df / 4; i += 32) {
        float4 w = row[i]; float4 c4 = cv[i];
        acc += w.x * c4.x + w.y * c4.y + w.z * c4.z + w.w * c4.w;
    }
    acc = warpsum(acc);
    if (lane == 0) g_qraw[e] = acc;
}

__global__ void k_qln(const float* __restrict__ lnw, const float* __restrict__ lnb) {
    __shared__ float red[32];
    int tid = threadIdx.x;
    float v[4];
    #pragma unroll
    for (int j = 0; j < 4; j++) v[j] = g_qraw[tid + j * 1024];
    float tot = blocksum(v[0] + v[1] + v[2] + v[3], red);
    float mu = tot * (1.f / Df);
    float q = 0.f;
    #pragma unroll
    for (int j = 0; j < 4; j++) { float dd = v[j] - mu; q += dd * dd; }
    float var = blocksum(q, red) * (1.f / Df);
    float inv = rsqrtf(var + 1e-5f);
    float Bp = 0.f, Cp = 0.f;
    #pragma unroll
    for (int j = 0; j < 4; j++) {
        int e = tid + j * 1024;
        float w = lnw[e], b = lnb[e];
        float qv = (v[j] - mu) * inv * w + b;
        float wq = w * qv;
        g_wq[e] = wq;
        Bp += wq;
        Cp += b * qv;
    }
    float Bt = blocksum(Bp, red);
    float Ct = blocksum(Cp, red);
    if (tid == 0) { g_Bs = Bt; g_Cs = Ct; }
}

__global__ void k_av1() {
    int dp = blockIdx.x * 256 + threadIdx.x;
    int ep = blockIdx.y;
    float sax = 0.f, say = 0.f, svx = 0.f, svy = 0.f;
    int e0 = ep * (Df / 8);
    for (int e = e0; e < e0 + Df / 8; e++) {
        float2 w = __half22float2(((const __half2*)(g_Wkh + (size_t)e * Df))[dp]);
        float wq = g_wq[e];
        sax += w.x; say += w.y;
        svx += wq * w.x; svy += wq * w.y;
    }
    g_ap[ep][2 * dp] = sax; g_ap[ep][2 * dp + 1] = say;
    g_vp[ep][2 * dp] = svx; g_vp[ep][2 * dp + 1] = svy;
}

__global__ void k_av2() {
    int d = blockIdx.x * 256 + threadIdx.x;
    float sa = 0.f, sv = 0.f;
    #pragma unroll
    for (int p = 0; p < 8; p++) { sa += g_ap[p][d]; sv += g_vp[p][d]; }
    g_a[d] = sa;
    g_v[d] = sv;
}

__global__ void k_s13() {
    int row = (blockIdx.x * 256 + threadIdx.x) >> 5;
    int lane = threadIdx.x & 31;
    const uint4* x = (const uint4*)(g_Xh + (size_t)row * Df);
    const float4* av = (const float4*)g_a;
    const float4* vv = (const float4*)g_v;
    float s1 = 0.f, s3 = 0.f;
    for (int i = lane; i < Df / 8; i += 32) {
        uint4 xx = x[i];
        float2 f0 = h2f(xx.x), f1 = h2f(xx.y), f2 = h2f(xx.z), f3 = h2f(xx.w);
        float4 a0 = av[2 * i], a1 = av[2 * i + 1];
        float4 v0 = vv[2 * i], v1 = vv[2 * i + 1];
        s1 += f0.x * a0.x + f0.y * a0.y + f1.x * a0.z + f1.y * a0.w
            + f2.x * a1.x + f2.y * a1.y + f3.x * a1.z + f3.y * a1.w;
        s3 += f0.x * v0.x + f0.y * v0.y + f1.x * v0.z + f1.y * v0.w
            + f2.x * v1.x + f2.y * v1.y + f3.x * v1.z + f3.y * v1.w;
    }
    s1 = warpsum(s1); s3 = warpsum(s3);
    if (lane == 0) { g_S1[row] = s1; g_S3[row] = s3; }
}

// ---------------- scores, z, topk, select, gather ----------------
__global__ void k_score() {
    int l = blockIdx.x;
    __shared__ float sc[Nf];
    __shared__ float red[32];
    int tid = threadIdx.x;
    float B = g_Bs, C = g_Cs;
    float part = 0.f;
    float loc[3];
    #pragma unroll
    for (int j = 0; j < 3; j++) {
        int n = tid + j * 192;
        int i = l * Nf + n;
        float s2 = 0.f;
        #pragma unroll
        for (int p = 0; p < GY; p++) s2 += g_S2part[p][i];
        float mu = g_S1[i] * (1.f / Df);
        float var = s2 * (1.f / Df) - mu * mu;
        float s = (g_S3[i] - mu * B) / sqrtf(var + 1e-5f) + C;
        sc[n] = s;
        loc[j] = s;
        part += s;
    }
    float mu_s = blocksum(part, red) * (1.f / Nf);
    float q = 0.f;
    #pragma unroll
    for (int j = 0; j < 3; j++) { float dd = loc[j] - mu_s; q += dd * dd; }
    float sd = sqrtf(blocksum(q, red) * (1.f / Nf));
    float inv = 1.f / (sd + 1e-6f);
    #pragma unroll
    for (int j = 0; j < 3; j++) {
        int n = tid + j * 192;
        g_zs[l][n] = (sc[n] - mu_s) * inv;
    }
}

__global__ void k_topk() {
    int l = blockIdx.x;
    __shared__ float sv[Nf];
    __shared__ float bv[8];
    __shared__ int bidx[8];
    int tid = threadIdx.x;
    int warp = tid >> 5, lane = tid & 31;
    for (int n = tid; n < Nf; n += 256) sv[n] = g_zs[l][n];
    __syncthreads();
    for (int t = 0; t < 64; t++) {
        float best = -3.4e38f;
        int besti = Nf;
        for (int n = tid; n < Nf; n += 256) {
            float v = sv[n];
            if (v > best || (v == best && n < besti)) { best = v; besti = n; }
        }
        #pragma unroll
        for (int o = 16; o; o >>= 1) {
            float ov = __shfl_xor_sync(0xffffffffu, best, o);
            int oi = __shfl_xor_sync(0xffffffffu, besti, o);
            if (ov > best || (ov == best && oi < besti)) { best = ov; besti = oi; }
        }
        if (lane == 0) { bv[warp] = best; bidx[warp] = besti; }
        __syncthreads();
        if (tid == 0) {
            float fb = bv[0]; int fi = bidx[0];
            #pragma unroll
            for (int w = 1; w < 8; w++)
                if (bv[w] > fb || (bv[w] == fb && bidx[w] < fi)) { fb = bv[w]; fi = bidx[w]; }
            g_topv[l][t] = fb;
            g_topi[l][t] = fi;
            sv[fi] = -3.4e38f;
        }
        __syncthreads();
    }
}

__global__ void k_select() {
    if (threadIdx.x != 0 || blockIdx.x != 0) return;
    float conf[Lf];
    for (int l = 0; l < Lf; l++) conf[l] = g_topv[l][0];

    int kper[Lf];
    for (int l = 0; l < Lf; l++) kper[l] = 0;
    kper[FOCUS] = 64;
    int rest = 64;

    int other[Lf]; int no = 0;
    for (int l = 0; l < Lf; l++)
        if (l != FOCUS && conf[l] > 2.0f) other[no++] = l;

    if (no > 0 && rest > 0) {
        float w[Lf];
        float mx = -3.4e38f;
        for (int j = 0; j < no; j++) if (conf[other[j]] > mx) mx = conf[other[j]];
        float sum = 0.f;
        for (int j = 0; j < no; j++) { w[j] = expf(conf[other[j]] - mx); sum += w[j]; }
        for (int j = 0; j < no; j++) w[j] /= sum;
        long long alloc[Lf]; long long asum = 0;
        for (int j = 0; j < no; j++) { alloc[j] = (long long)floorf(w[j] * (float)rest); asum += alloc[j]; }
        long long rem = rest - asum;
        bool used[Lf];
        for (int j = 0; j < no; j++) used[j] = false;
        for (int t = 0; t < no && rem > 0; t++) {
            int best = -1;
            for (int j = 0; j < no; j++)
                if (!used[j] && (best < 0 || w[j] > w[best])) best = j;
            used[best] = true;
            alloc[best]++; rem--;
        }
        for (int j = 0; j < no; j++)
            if (alloc[j] > 0) {
                int v = (int)alloc[j];
                kper[other[j]] = v < Nf ? v : Nf;
            }
    }

    float sc[192]; int fli[192], fidx[192]; int M = 0;
    for (int l = 0; l < Lf; l++) {
        int kl = kper[l];
        for (int t = 0; t < kl; t++) {
            fli[M] = l; fidx[M] = g_topi[l][t]; sc[M] = g_topv[l][t]; M++;
        }
    }

    int final_k = M < 64 ? M : 64;
    int focus_min = final_k < 32 ? final_k : 32;

    int sel[64]; int ns = 0;
    bool taken[192];
    for (int m = 0; m < M; m++) taken[m] = false;

    for (int t = 0; t < focus_min; t++) {
        int best = -1;
        for (int m = 0; m < M; m++)
            if (fli[m] == FOCUS && !taken[m] && (best < 0 || sc[m] > sc[best])) best = m;
        if (best < 0) break;
        taken[best] = true; sel[ns++] = best;
    }
    int remain = final_k - ns;
    for (int t = 0; t < remain; t++) {
        int best = -1;
        for (int m = 0; m < M; m++)
            if (!taken[m] && (best < 0 || sc[m] > sc[best])) best = m;
        if (best < 0) break;
        taken[best] = true; sel[ns++] = best;
    }
    for (int i = 0; i < ns; i++) {
        int bj = i;
        for (int j = i + 1; j < ns; j++)
            if (sc[sel[j]] > sc[sel[bj]]) bj = j;
        int tmp = sel[i]; sel[i] = sel[bj]; sel[bj] = tmp;
    }
    for (int i = 0; i < ns; i++) {
        g_sel_li[i] = fli[sel[i]];
        g_sel_idx[i] = fidx[sel[i]];
    }
}

__global__ void k_gather(const float* __restrict__ proj, float* __restrict__ out) {
    int j = blockIdx.x;
    int li = g_sel_li[j], idx = g_sel_idx[j];
    const float4* src = (const float4*)(proj + ((size_t)li * Nf + idx) * Df);
    float4* dst = (float4*)(out + (size_t)j * Df);
    for (int i = threadIdx.x; i < Df / 4; i += blockDim.x) dst[i] = src[i];
}

// ---------------- launch ----------------
extern "C" void kernel_launch(void* const* d_in, const int* in_sizes, int n_in,
                              void* d_out, int out_size) {
    const float* text = (const float*)d_in[0];
    const float* proj = (const float*)d_in[1];
    const float* Wq   = (const float*)d_in[2];
    const float* Wk   = (const float*)d_in[3];
    const float* lnw  = (const float*)d_in[4];
    const float* lnb  = (const float*)d_in[5];
    const float* W1w  = (const float*)d_in[6];
    const float* W1b  = (const float*)d_in[7];
    const float* Wcw  = (const float*)d_in[8];
    const float* Wcb  = (const float*)d_in[9];
    const float* Wiw  = (const float*)d_in[10];
    const float* Wib  = (const float*)d_in[11];
    const float* Wfw  = (const float*)d_in[12];
    const float* Wfb  = (const float*)d_in[13];
    const float* bc   = (const float*)d_in[14];
    const float* bi   = (const float*)d_in[15];
    const float* bf   = (const float*)d_in[16];
    float* out = (float*)d_out;

    static cudaStream_t s_side = nullptr;
    static cudaEvent_t ev_fork = nullptr, ev_join = nullptr;
    static bool attr_done = false;
    if (s_side == nullptr) {
        cudaStreamCreateWithFlags(&s_side, cudaStreamNonBlocking);
        cudaEventCreateWithFlags(&ev_fork, cudaEventDisableTiming);
        cudaEventCreateWithFlags(&ev_join, cudaEventDisableTiming);
    }
    if (!attr_done) {
        cudaFuncSetAttribute(k_s2h, cudaFuncAttributeMaxDynamicSharedMemorySize,
                             STG * STGB);
        attr_done = true;
    }

    // #1: fp32->fp16 conversion of proj + Wk (main stream)
    k_conv<<<(XN + WN) / 8 / 256, 256>>>(proj, Wk);
    // fork AFTER conv so side chain may use g_Xh/g_Wkh
    cudaEventRecord(ev_fork, 0);
    cudaStreamWaitEvent(s_side, ev_fork, 0);

    // #2: DSU weight conversion (side), #3: init (side)
    k_conv2<<<(A1 + 3 * A2) / 8 / 256, 256, 0, s_side>>>(W1w, Wcw, Wiw, Wfw);
    k_init<<<16, 256, 0, s_side>>>();
    // #4: GEMM (sampled by ncu), main stream
    k_s2h<<<dim3(MROWS / BM, GY), 512, STG * STGB>>>();

    // side chain (overlaps GEMM)
    k_tg1<<<16, 256, 0, s_side>>>(text);
    k_tg2<<<1, 1024, 0, s_side>>>();
    k_y_h<<<dim3(8, Lf), 256, 0, s_side>>>();
    k_pres<<<128, 256, 0, s_side>>>(W1w, W1b);
    for (int l = 0; l < NSTEP; l++) {
        k_step_s<<<128, 256, 0, s_side>>>(l);
        k_step_c<<<512, 256, 0, s_side>>>(Wcb, Wib, Wfb, bc, bi, bf);
    }
    k_qraw<<<512, 256, 0, s_side>>>(Wq);
    k_qln<<<1, 1024, 0, s_side>>>(lnw, lnb);
    k_av1<<<dim3(8, 8), 256, 0, s_side>>>();
    k_av2<<<16, 256, 0, s_side>>>();
    k_s13<<<MROWS / 8, 256, 0, s_side>>>();

    cudaEventRecord(ev_join, s_side);
    cudaStreamWaitEvent(0, ev_join, 0);

    k_score<<<Lf, 192>>>();
    k_topk<<<Lf, 256>>>();
    k_select<<<1, 32>>>();
    k_gather<<<64, 256>>>(proj, out);
}

// round 17
// speedup vs baseline: 1.7518x; 1.0727x over previous
#include <cuda_runtime.h>
#include <cuda_fp16.h>
#include <cstdint>

#define Df 4096
#define Lf 24
#define Nf 576
#define Tf 128
#define REDf 1024
#define MROWS (Lf*Nf)
#define NSTEP 23
#define FOCUS 22
#define GY 16

#define BM 128
#define BN 256
#define NCH 128
#define STG 6
#define STGB 30720
#define XN (MROWS*Df)
#define WN (Df*Df)
#define A1 (REDf*Df)
#define A2 (Df*REDf)

// ---------------- device scratch ----------------
__device__ __half g_Xh[XN];
__device__ __half g_Wkh[WN];
__device__ __half g_W1h[REDf*Df];
__device__ __half g_Wch[Df*REDf];
__device__ __half g_Wih[Df*REDf];
__device__ __half g_Wfh[Df*REDf];
__device__ float g_tgm[Df];
__device__ float g_tg[Df];
__device__ float g_y[Lf][Df];
__device__ float g_pres[NSTEP][REDf];
__device__ float g_c[Df];
__device__ float g_sc[Df];
__device__ float g_s[REDf];
__device__ float g_qraw[Df];
__device__ float g_wq[Df];
__device__ float g_Bs, g_Cs;
__device__ float g_ap[8][Df];
__device__ float g_vp[8][Df];
__device__ float g_a[Df];
__device__ float g_v[Df];
__device__ float g_S1[MROWS];
__device__ float g_S2part[GY][MROWS];
__device__ float g_S3[MROWS];
__device__ float g_zs[Lf][Nf];
__device__ float g_topv[Lf][64];
__device__ int   g_topi[Lf][64];
__device__ int   g_sel_li[64];
__device__ int   g_sel_idx[64];

// ---------------- helpers ----------------
__device__ __forceinline__ float warpsum(float v) {
    #pragma unroll
    for (int o = 16; o; o >>= 1) v += __shfl_xor_sync(0xffffffffu, v, o);
    return v;
}

__device__ __forceinline__ float blocksum(float v, float* red) {
    int tid = threadIdx.x, ln = tid & 31, w = tid >> 5, nw = blockDim.x >> 5;
    float s = warpsum(v);
    if (ln == 0) red[w] = s;
    __syncthreads();
    if (w == 0) {
        float r = (ln < nw) ? red[ln] : 0.f;
        r = warpsum(r);
        if (ln == 0) red[0] = r;
    }
    __syncthreads();
    float out = red[0];
    __syncthreads();
    return out;
}

__device__ __forceinline__ float sigm_(float x) { return 1.f / (1.f + expf(-x)); }

__device__ __forceinline__ uint32_t smem_u32(const void* p) {
    uint32_t a;
    asm("{ .reg .u64 t; cvta.to.shared.u64 t, %1; cvt.u32.u64 %0, t; }" : "=r"(a) : "l"(p));
    return a;
}

__device__ __forceinline__ void mma_f16(float c[4], uint32_t a0, uint32_t a1,
                                        uint32_t a2, uint32_t a3,
                                        uint32_t b0, uint32_t b1) {
    asm volatile(
        "mma.sync.aligned.m16n8k16.row.col.f32.f16.f16.f32 "
        "{%0,%1,%2,%3}, {%4,%5,%6,%7}, {%8,%9}, {%0,%1,%2,%3};\n"
        : "+f"(c[0]), "+f"(c[1]), "+f"(c[2]), "+f"(c[3])
        : "r"(a0), "r"(a1), "r"(a2), "r"(a3), "r"(b0), "r"(b1));
}

#define LDSM4(r0, r1, r2, r3, addr) \
    asm volatile("ldmatrix.sync.aligned.m8n8.x4.shared.b16 {%0,%1,%2,%3}, [%4];" \
                 : "=r"(r0), "=r"(r1), "=r"(r2), "=r"(r3) : "r"(addr))

#define CPA16(dst, src) \
    asm volatile("cp.async.cg.shared.global [%0], [%1], 16;" :: "r"(dst), "l"(src) : "memory")
#define CPA_COMMIT() asm volatile("cp.async.commit_group;" ::: "memory")
#define CPA_WAIT2()  asm volatile("cp.async.wait_group 2;" ::: "memory")

__device__ __forceinline__ uint32_t pack_h2(float lo, float hi) {
    __half2 h = __floats2half2_rn(lo, hi);
    return reinterpret_cast<uint32_t&>(h);
}

__device__ __forceinline__ float2 h2f(uint32_t u) {
    __half2 h = *reinterpret_cast<__half2*>(&u);
    return __half22float2(h);
}

// ---------------- conversions ----------------
__global__ void k_conv(const float* __restrict__ X, const float* __restrict__ Wk) {
    size_t i = ((size_t)blockIdx.x * 256 + threadIdx.x) * 8;
    const float* src; __half* dst; size_t off;
    if (i < (size_t)XN) { src = X; dst = g_Xh; off = i; }
    else { src = Wk; dst = g_Wkh; off = i - (size_t)XN; }
    float4 a = *(const float4*)(src + off);
    float4 b = *(const float4*)(src + off + 4);
    uint4 o;
    o.x = pack_h2(a.x, a.y); o.y = pack_h2(a.z, a.w);
    o.z = pack_h2(b.x, b.y); o.w = pack_h2(b.z, b.w);
    *(uint4*)(dst + off) = o;
}

__global__ void k_conv2(const float* __restrict__ W1w, const float* __restrict__ Wc,
                        const float* __restrict__ Wi, const float* __restrict__ Wf) {
    size_t j = ((size_t)blockIdx.x * 256 + threadIdx.x) * 8;
    const float* src; __half* dst;
    if (j < (size_t)A1) {
        size_t r = j / Df, dcol = j - r * Df;
        src = W1w + r * (3 * (size_t)Df) + dcol;
        dst = g_W1h + j;
    } else if (j < (size_t)A1 + A2) { size_t o = j - A1; src = Wc + o; dst = g_Wch + o; }
    else if (j < (size_t)A1 + 2 * A2) { size_t o = j - A1 - A2; src = Wi + o; dst = g_Wih + o; }
    else { size_t o = j - A1 - 2 * (size_t)A2; src = Wf + o; dst = g_Wfh + o; }
    float4 a = *(const float4*)src;
    float4 b = *(const float4*)(src + 4);
    uint4 o;
    o.x = pack_h2(a.x, a.y); o.y = pack_h2(a.z, a.w);
    o.z = pack_h2(b.x, b.y); o.w = pack_h2(b.z, b.w);
    *(uint4*)dst = o;
}

// ---------------- small kernels ----------------
__global__ void k_init() {
    int d = blockIdx.x * blockDim.x + threadIdx.x;
    if (d < Df) { g_c[d] = 0.f; g_sc[d] = 0.5f; }
}

__global__ void k_tg1(const float* __restrict__ text) {
    int d = blockIdx.x * blockDim.x + threadIdx.x;
    float s = 0.f;
    for (int t = 0; t < Tf; t++) s += text[(size_t)t * Df + d];
    g_tgm[d] = s * (1.0f / Tf);
}

__global__ void k_tg2() {
    __shared__ float red[32];
    int tid = threadIdx.x;
    float v[4];
    #pragma unroll
    for (int j = 0; j < 4; j++) v[j] = g_tgm[tid + j * 1024];
    float tot = blocksum(v[0] + v[1] + v[2] + v[3], red);
    float mu = tot * (1.f / Df);
    float q = 0.f;
    #pragma unroll
    for (int j = 0; j < 4; j++) { float dd = v[j] - mu; q += dd * dd; }
    float var = blocksum(q, red) * (1.f / Df);
    float inv = rsqrtf(var + 1e-5f);
    #pragma unroll
    for (int j = 0; j < 4; j++) g_tg[tid + j * 1024] = (v[j] - mu) * inv;
}

__global__ void k_y_h() {
    int l = blockIdx.y;
    int dp = blockIdx.x * 256 + threadIdx.x;
    const __half2* p = (const __half2*)(g_Xh + (size_t)l * Nf * Df) + dp;
    float sx = 0.f, sy = 0.f;
    for (int n = 0; n < Nf; n++) {
        float2 v = __half22float2(p[(size_t)n * (Df / 2)]);
        sx += v.x; sy += v.y;
    }
    g_y[l][2 * dp] = sx * (1.0f / Nf);
    g_y[l][2 * dp + 1] = sy * (1.0f / Nf);
}

__global__ void k_pres(const float* __restrict__ W1w, const float* __restrict__ W1b) {
    int warp = (blockIdx.x * blockDim.x + threadIdx.x) >> 5;
    int lane = threadIdx.x & 31;
    if (warp >= REDf) return;
    const float* rowY = W1w + (size_t)warp * (3 * Df) + Df;
    const float* rowT = rowY + Df;
    float accT = 0.f;
    float accL[NSTEP];
    #pragma unroll
    for (int l = 0; l < NSTEP; l++) accL[l] = 0.f;
    for (int d = lane; d < Df; d += 32) {
        float wy = rowY[d];
        float wt = rowT[d];
        accT += wt * g_tg[d];
        #pragma unroll
        for (int l = 0; l < NSTEP; l++) accL[l] += wy * g_y[l][d];
    }
    accT = warpsum(accT);
    #pragma unroll
    for (int l = 0; l < NSTEP; l++) accL[l] = warpsum(accL[l]);
    if (lane == 0) {
        float base = W1b[warp] + accT;
        #pragma unroll
        for (int l = 0; l < NSTEP; l++) g_pres[l][warp] = base + accL[l];
    }
}

// ------- fused S2 GEMM: 128x256 tile, 6-stage, 2 chunks per barrier ----------
__global__ void __launch_bounds__(512, 1) k_s2h() {
    extern __shared__ __half sh[];
    uint32_t sbase = smem_u32(sh);
    int tid = threadIdx.x;
    int lane = tid & 31, warp = tid >> 5;
    int wm = warp >> 2, wn = warp & 3;
    int g = lane >> 2;
    int row_block = blockIdx.x * BM;
    int e0 = blockIdx.y * BN;

    int arow = lane & 15;
    int akoff = (lane >> 4) * 8;
    int brow = (lane & 7) + ((lane & 16) >> 1);
    int bkoff = (lane & 8) ? 8 : 0;

    float acc[2][8][4];
    #pragma unroll
    for (int mt = 0; mt < 2; mt++)
        #pragma unroll
        for (int ni = 0; ni < 8; ni++)
            #pragma unroll
            for (int r = 0; r < 4; r++) acc[mt][ni][r] = 0.f;

    int arow_ld = tid >> 2, aq_ld = tid & 3;

    auto issue = [&](int c) {
        int sl = c % STG;
        int kb = c * 32;
        {
            const __half* sa = g_Xh + (size_t)(row_block + arow_ld) * Df + kb + aq_ld * 8;
            uint32_t da = sbase + (uint32_t)(sl * STGB + arow_ld * 80 + aq_ld * 16);
            CPA16(da, sa);
        }
        #pragma unroll
        for (int i = 0; i < 2; i++) {
            int seg = tid * 2 + i;
            int row = seg >> 2, q = seg & 3;
            const __half* sb = g_Wkh + (size_t)(e0 + row) * Df + kb + q * 8;
            uint32_t db = sbase + (uint32_t)(sl * STGB + 10240 + row * 80 + q * 16);
            CPA16(db, sb);
        }
    };

    auto compute = [&](int c) {
        int sl = c % STG;
        uint32_t abase = sbase + sl * STGB;
        uint32_t bbase = abase + 10240;
        #pragma unroll
        for (int kk = 0; kk < 2; kk++) {
            uint32_t a0[4], a1[4];
            uint32_t aaddr = abase + (uint32_t)((wm * 32 + arow) * 80 + (kk * 16 + akoff) * 2);
            LDSM4(a0[0], a0[1], a0[2], a0[3], aaddr);
            LDSM4(a1[0], a1[1], a1[2], a1[3], aaddr + 16 * 80);
            #pragma unroll
            for (int p = 0; p < 4; p++) {
                uint32_t b[4];
                uint32_t baddr = bbase + (uint32_t)((wn * 64 + p * 16 + brow) * 80 + (kk * 16 + bkoff) * 2);
                LDSM4(b[0], b[1], b[2], b[3], baddr);
                mma_f16(acc[0][2 * p],     a0[0], a0[1], a0[2], a0[3], b[0], b[1]);
                mma_f16(acc[0][2 * p + 1], a0[0], a0[1], a0[2], a0[3], b[2], b[3]);
                mma_f16(acc[1][2 * p],     a1[0], a1[1], a1[2], a1[3], b[0], b[1]);
                mma_f16(acc[1][2 * p + 1], a1[0], a1[1], a1[2], a1[3], b[2], b[3]);
            }
        }
    };

    issue(0); CPA_COMMIT();
    issue(1); CPA_COMMIT();
    issue(2); CPA_COMMIT();
    issue(3); CPA_COMMIT();

    for (int cp = 0; cp < NCH / 2; ++cp) {
        int c0 = 2 * cp;
        CPA_WAIT2();                 // 4 pending -> oldest 2 (c0, c0+1) done
        __syncthreads();             // all warps done with pair cp-1 slots
        compute(c0);
        if (c0 + 4 < NCH) issue(c0 + 4);   // slot of chunk c0-2 (consumed pair cp-1)
        CPA_COMMIT();
        compute(c0 + 1);
        if (c0 + 5 < NCH) issue(c0 + 5);   // slot of chunk c0-1 (consumed pair cp-1)
        CPA_COMMIT();
    }

    float s2p[4];
    #pragma unroll
    for (int mt = 0; mt < 2; mt++) {
        float p0 = 0.f, p1 = 0.f;
        #pragma unroll
        for (int ni = 0; ni < 8; ni++) {
            p0 += acc[mt][ni][0] * acc[mt][ni][0] + acc[mt][ni][1] * acc[mt][ni][1];
            p1 += acc[mt][ni][2] * acc[mt][ni][2] + acc[mt][ni][3] * acc[mt][ni][3];
        }
        s2p[mt * 2 + 0] = p0;
        s2p[mt * 2 + 1] = p1;
    }
    #pragma unroll
    for (int j = 0; j < 4; j++) {
        s2p[j] += __shfl_xor_sync(0xffffffffu, s2p[j], 1);
        s2p[j] += __shfl_xor_sync(0xffffffffu, s2p[j], 2);
    }
    __syncthreads();
    float* s2sh = (float*)sh;
    if ((lane & 3) == 0) {
        s2sh[wn * BM + wm * 32 + g]      = s2p[0];
        s2sh[wn * BM + wm * 32 + g + 8]  = s2p[1];
        s2sh[wn * BM + wm * 32 + g + 16] = s2p[2];
        s2sh[wn * BM + wm * 32 + g + 24] = s2p[3];
    }
    __syncthreads();
    if (tid < BM) {
        float s = s2sh[tid] + s2sh[BM + tid] + s2sh[2 * BM + tid] + s2sh[3 * BM + tid];
        g_S2part[blockIdx.y][row_block + tid] = s;
    }
}

// ---------------- DSU / q pipeline (fp16 weights) ----------------
__global__ void k_step_s(int l) {
    int warp = (blockIdx.x * 256 + threadIdx.x) >> 5;
    int lane = threadIdx.x & 31;
    const uint4* row = (const uint4*)(g_W1h + (size_t)warp * Df);
    const float4* scv = (const float4*)g_sc;
    float acc = 0.f;
    for (int i = lane; i < Df / 8; i += 32) {
        uint4 w = row[i];
        float4 s0 = scv[2 * i], s1 = scv[2 * i + 1];
        float2 f0 = h2f(w.x), f1 = h2f(w.y), f2 = h2f(w.z), f3 = h2f(w.w);
        acc += f0.x * s0.x + f0.y * s0.y + f1.x * s0.z + f1.y * s0.w
             + f2.x * s1.x + f2.y * s1.y + f3.x * s1.z + f3.y * s1.w;
    }
    acc = warpsum(acc);
    if (lane == 0) {
        float v = g_pres[l][warp] + acc;
        g_s[warp] = v > 0.f ? v : 0.f;
    }
}

__global__ void k_step_c(const float* __restrict__ Wcb, const float* __restrict__ Wib,
                         const float* __restrict__ Wfb,
                         const float* __restrict__ bc, const float* __restrict__ bi,
                         const float* __restrict__ bf) {
    int d = (blockIdx.x * 256 + threadIdx.x) >> 5;
    int lane = threadIdx.x & 31;
    const uint4* rc = (const uint4*)(g_Wch + (size_t)d * REDf);
    const uint4* ri = (const uint4*)(g_Wih + (size_t)d * REDf);
    const uint4* rf = (const uint4*)(g_Wfh + (size_t)d * REDf);
    const float4* sv = (const float4*)g_s;
    float ac = 0.f, ai = 0.f, af = 0.f;
    for (int i = lane; i < REDf / 8; i += 32) {
        float4 s0 = sv[2 * i], s1 = sv[2 * i + 1];
        uint4 c8 = rc[i];
        {
            float2 f0 = h2f(c8.x), f1 = h2f(c8.y), f2 = h2f(c8.z), f3 = h2f(c8.w);
            ac += f0.x * s0.x + f0.y * s0.y + f1.x * s0.z + f1.y * s0.w
                + f2.x * s1.x + f2.y * s1.y + f3.x * s1.z + f3.y * s1.w;
        }
        uint4 i8 = ri[i];
        {
            float2 f0 = h2f(i8.x), f1 = h2f(i8.y), f2 = h2f(i8.z), f3 = h2f(i8.w);
            ai += f0.x * s0.x + f0.y * s0.y + f1.x * s0.z + f1.y * s0.w
                + f2.x * s1.x + f2.y * s1.y + f3.x * s1.z + f3.y * s1.w;
        }
        uint4 f8 = rf[i];
        {
            float2 f0 = h2f(f8.x), f1 = h2f(f8.y), f2 = h2f(f8.z), f3 = h2f(f8.w);
            af += f0.x * s0.x + f0.y * s0.y + f1.x * s0.z + f1.y * s0.w
                + f2.x * s1.x + f2.y * s1.y + f3.x * s1.z + f3.y * s1.w;
        }
    }
    ac = warpsum(ac); ai = warpsum(ai); af = warpsum(af);
    if (lane == 0) {
        float ct = tanhf(ac + Wcb[d] + bc[d]);
        float iv = sigm_(ai + Wib[d] + bi[d]);
        float fv = sigm_(af + Wfb[d] + bf[d]);
        float cn = fv * g_c[d] + iv * ct;
        g_c[d] = cn;
        g_sc[d] = sigm_(cn);
    }
}

__global__ void k_qraw(const float* __restrict__ Wq) {
    int e = (blockIdx.x * 256 + threadIdx.x) >> 5;
    int lane = threadIdx.x & 31;
    const float4* row = (const float4*)(Wq + (size_t)e * Df);
    const float4* cv = (const float4*)g_c;
    float acc = 0.f;
    for (int i = lane; i < Df / 4; i += 32) {
        float4 w = row[i]; float4 c4 = cv[i];
        acc += w.x * c4.x + w.y * c4.y + w.z * c4.z + w.w * c4.w;
    }
    acc = warpsum(acc);
    if (lane == 0) g_qraw[e] = acc;
}

__global__ void k_qln(const float* __restrict__ lnw, const float* __restrict__ lnb) {
    __shared__ float red[32];
    int tid = threadIdx.x;
    float v[4];
    #pragma unroll
    for (int j = 0; j < 4; j++) v[j] = g_qraw[tid + j * 1024];
    float tot = blocksum(v[0] + v[1] + v[2] + v[3], red);
    float mu = tot * (1.f / Df);
    float q = 0.f;
    #pragma unroll
    for (int j = 0; j < 4; j++) { float dd = v[j] - mu; q += dd * dd; }
    float var = blocksum(q, red) * (1.f / Df);
    float inv = rsqrtf(var + 1e-5f);
    float Bp = 0.f, Cp = 0.f;
    #pragma unroll
    for (int j = 0; j < 4; j++) {
        int e = tid + j * 1024;
        float w = lnw[e], b = lnb[e];
        float qv = (v[j] - mu) * inv * w + b;
        float wq = w * qv;
        g_wq[e] = wq;
        Bp += wq;
        Cp += b * qv;
    }
    float Bt = blocksum(Bp, red);
    float Ct = blocksum(Cp, red);
    if (tid == 0) { g_Bs = Bt; g_Cs = Ct; }
}

__global__ void k_av1() {
    int dp = blockIdx.x * 256 + threadIdx.x;
    int ep = blockIdx.y;
    float sax = 0.f, say = 0.f, svx = 0.f, svy = 0.f;
    int e0 = ep * (Df / 8);
    for (int e = e0; e < e0 + Df / 8; e++) {
        float2 w = __half22float2(((const __half2*)(g_Wkh + (size_t)e * Df))[dp]);
        float wq = g_wq[e];
        sax += w.x; say += w.y;
        svx += wq * w.x; svy += wq * w.y;
    }
    g_ap[ep][2 * dp] = sax; g_ap[ep][2 * dp + 1] = say;
    g_vp[ep][2 * dp] = svx; g_vp[ep][2 * dp + 1] = svy;
}

__global__ void k_av2() {
    int d = blockIdx.x * 256 + threadIdx.x;
    float sa = 0.f, sv = 0.f;
    #pragma unroll
    for (int p = 0; p < 8; p++) { sa += g_ap[p][d]; sv += g_vp[p][d]; }
    g_a[d] = sa;
    g_v[d] = sv;
}

__global__ void k_s13() {
    int row = (blockIdx.x * 256 + threadIdx.x) >> 5;
    int lane = threadIdx.x & 31;
    const uint4* x = (const uint4*)(g_Xh + (size_t)row * Df);
    const float4* av = (const float4*)g_a;
    const float4* vv = (const float4*)g_v;
    float s1 = 0.f, s3 = 0.f;
    for (int i = lane; i < Df / 8; i += 32) {
        uint4 xx = x[i];
        float2 f0 = h2f(xx.x), f1 = h2f(xx.y), f2 = h2f(xx.z), f3 = h2f(xx.w);
        float4 a0 = av[2 * i], a1 = av[2 * i + 1];
        float4 v0 = vv[2 * i], v1 = vv[2 * i + 1];
        s1 += f0.x * a0.x + f0.y * a0.y + f1.x * a0.z + f1.y * a0.w
            + f2.x * a1.x + f2.y * a1.y + f3.x * a1.z + f3.y * a1.w;
        s3 += f0.x * v0.x + f0.y * v0.y + f1.x * v0.z + f1.y * v0.w
            + f2.x * v1.x + f2.y * v1.y + f3.x * v1.z + f3.y * v1.w;
    }
    s1 = warpsum(s1); s3 = warpsum(s3);
    if (lane == 0) { g_S1[row] = s1; g_S3[row] = s3; }
}

// ---------------- scores, z, topk, select, gather ----------------
__global__ void k_score() {
    int l = blockIdx.x;
    __shared__ float sc[Nf];
    __shared__ float red[32];
    int tid = threadIdx.x;
    float B = g_Bs, C = g_Cs;
    float part = 0.f;
    float loc[3];
    #pragma unroll
    for (int j = 0; j < 3; j++) {
        int n = tid + j * 192;
        int i = l * Nf + n;
        float s2 = 0.f;
        #pragma unroll
        for (int p = 0; p < GY; p++) s2 += g_S2part[p][i];
        float mu = g_S1[i] * (1.f / Df);
        float var = s2 * (1.f / Df) - mu * mu;
        float s = (g_S3[i] - mu * B) / sqrtf(var + 1e-5f) + C;
        sc[n] = s;
        loc[j] = s;
        part += s;
    }
    float mu_s = blocksum(part, red) * (1.f / Nf);
    float q = 0.f;
    #pragma unroll
    for (int j = 0; j < 3; j++) { float dd = loc[j] - mu_s; q += dd * dd; }
    float sd = sqrtf(blocksum(q, red) * (1.f / Nf));
    float inv = 1.f / (sd + 1e-6f);
    #pragma unroll
    for (int j = 0; j < 3; j++) {
        int n = tid + j * 192;
        g_zs[l][n] = (sc[n] - mu_s) * inv;
    }
}

__global__ void k_topk() {
    int l = blockIdx.x;
    __shared__ float sv[Nf];
    __shared__ float bv[8];
    __shared__ int bidx[8];
    int tid = threadIdx.x;
    int warp = tid >> 5, lane = tid & 31;
    for (int n = tid; n < Nf; n += 256) sv[n] = g_zs[l][n];
    __syncthreads();
    for (int t = 0; t < 64; t++) {
        float best = -3.4e38f;
        int besti = Nf;
        for (int n = tid; n < Nf; n += 256) {
            float v = sv[n];
            if (v > best || (v == best && n < besti)) { best = v; besti = n; }
        }
        #pragma unroll
        for (int o = 16; o; o >>= 1) {
            float ov = __shfl_xor_sync(0xffffffffu, best, o);
            int oi = __shfl_xor_sync(0xffffffffu, besti, o);
            if (ov > best || (ov == best && oi < besti)) { best = ov; besti = oi; }
        }
        if (lane == 0) { bv[warp] = best; bidx[warp] = besti; }
        __syncthreads();
        if (tid == 0) {
            float fb = bv[0]; int fi = bidx[0];
            #pragma unroll
            for (int w = 1; w < 8; w++)
                if (bv[w] > fb || (bv[w] == fb && bidx[w] < fi)) { fb = bv[w]; fi = bidx[w]; }
            g_topv[l][t] = fb;
            g_topi[l][t] = fi;
            sv[fi] = -3.4e38f;
        }
        __syncthreads();
    }
}

__global__ void k_select() {
    if (threadIdx.x != 0 || blockIdx.x != 0) return;
    float conf[Lf];
    for (int l = 0; l < Lf; l++) conf[l] = g_topv[l][0];

    int kper[Lf];
    for (int l = 0; l < Lf; l++) kper[l] = 0;
    kper[FOCUS] = 64;
    int rest = 64;

    int other[Lf]; int no = 0;
    for (int l = 0; l < Lf; l++)
        if (l != FOCUS && conf[l] > 2.0f) other[no++] = l;

    if (no > 0 && rest > 0) {
        float w[Lf];
        float mx = -3.4e38f;
        for (int j = 0; j < no; j++) if (conf[other[j]] > mx) mx = conf[other[j]];
        float sum = 0.f;
        for (int j = 0; j < no; j++) { w[j] = expf(conf[other[j]] - mx); sum += w[j]; }
        for (int j = 0; j < no; j++) w[j] /= sum;
        long long alloc[Lf]; long long asum = 0;
        for (int j = 0; j < no; j++) { alloc[j] = (long long)floorf(w[j] * (float)rest); asum += alloc[j]; }
        long long rem = rest - asum;
        bool used[Lf];
        for (int j = 0; j < no; j++) used[j] = false;
        for (int t = 0; t < no && rem > 0; t++) {
            int best = -1;
            for (int j = 0; j < no; j++)
                if (!used[j] && (best < 0 || w[j] > w[best])) best = j;
            used[best] = true;
            alloc[best]++; rem--;
        }
        for (int j = 0; j < no; j++)
            if (alloc[j] > 0) {
                int v = (int)alloc[j];
                kper[other[j]] = v < Nf ? v : Nf;
            }
    }

    float sc[192]; int fli[192], fidx[192]; int M = 0;
    for (int l = 0; l < Lf; l++) {
        int kl = kper[l];
        for (int t = 0; t < kl; t++) {
            fli[M] = l; fidx[M] = g_topi[l][t]; sc[M] = g_topv[l][t]; M++;
        }
    }

    int final_k = M < 64 ? M : 64;
    int focus_min = final_k < 32 ? final_k : 32;

    int sel[64]; int ns = 0;
    bool taken[192];
    for (int m = 0; m < M; m++) taken[m] = false;

    for (int t = 0; t < focus_min; t++) {
        int best = -1;
        for (int m = 0; m < M; m++)
            if (fli[m] == FOCUS && !taken[m] && (best < 0 || sc[m] > sc[best])) best = m;
        if (best < 0) break;
        taken[best] = true; sel[ns++] = best;
    }
    int remain = final_k - ns;
    for (int t = 0; t < remain; t++) {
        int best = -1;
        for (int m = 0; m < M; m++)
            if (!taken[m] && (best < 0 || sc[m] > sc[best])) best = m;
        if (best < 0) break;
        taken[best] = true; sel[ns++] = best;
    }
    for (int i = 0; i < ns; i++) {
        int bj = i;
        for (int j = i + 1; j < ns; j++)
            if (sc[sel[j]] > sc[sel[bj]]) bj = j;
        int tmp = sel[i]; sel[i] = sel[bj]; sel[bj] = tmp;
    }
    for (int i = 0; i < ns; i++) {
        g_sel_li[i] = fli[sel[i]];
        g_sel_idx[i] = fidx[sel[i]];
    }
}

__global__ void k_gather(const float* __restrict__ proj, float* __restrict__ out) {
    int j = blockIdx.x;
    int li = g_sel_li[j], idx = g_sel_idx[j];
    const float4* src = (const float4*)(proj + ((size_t)li * Nf + idx) * Df);
    float4* dst = (float4*)(out + (size_t)j * Df);
    for (int i = threadIdx.x; i < Df / 4; i += blockDim.x) dst[i] = src[i];
}

// ---------------- launch ----------------
extern "C" void kernel_launch(void* const* d_in, const int* in_sizes, int n_in,
                              void* d_out, int out_size) {
    const float* text = (const float*)d_in[0];
    const float* proj = (const float*)d_in[1];
    const float* Wq   = (const float*)d_in[2];
    const float* Wk   = (const float*)d_in[3];
    const float* lnw  = (const float*)d_in[4];
    const float* lnb  = (const float*)d_in[5];
    const float* W1w  = (const float*)d_in[6];
    const float* W1b  = (const float*)d_in[7];
    const float* Wcw  = (const float*)d_in[8];
    const float* Wcb  = (const float*)d_in[9];
    const float* Wiw  = (const float*)d_in[10];
    const float* Wib  = (const float*)d_in[11];
    const float* Wfw  = (const float*)d_in[12];
    const float* Wfb  = (const float*)d_in[13];
    const float* bc   = (const float*)d_in[14];
    const float* bi   = (const float*)d_in[15];
    const float* bf   = (const float*)d_in[16];
    float* out = (float*)d_out;

    static cudaStream_t s_side = nullptr;
    static cudaEvent_t ev_fork = nullptr, ev_join = nullptr;
    static bool attr_done = false;
    if (s_side == nullptr) {
        cudaStreamCreateWithFlags(&s_side, cudaStreamNonBlocking);
        cudaEventCreateWithFlags(&ev_fork, cudaEventDisableTiming);
        cudaEventCreateWithFlags(&ev_join, cudaEventDisableTiming);
    }
    if (!attr_done) {
        cudaFuncSetAttribute(k_s2h, cudaFuncAttributeMaxDynamicSharedMemorySize,
                             STG * STGB);
        attr_done = true;
    }

    // #1: fp32->fp16 conversion of proj + Wk (main stream)
    k_conv<<<(XN + WN) / 8 / 256, 256>>>(proj, Wk);
    // fork AFTER conv so side chain may use g_Xh/g_Wkh
    cudaEventRecord(ev_fork, 0);
    cudaStreamWaitEvent(s_side, ev_fork, 0);

    // #2: DSU weight conversion (side), #3: init (side)
    k_conv2<<<(A1 + 3 * A2) / 8 / 256, 256, 0, s_side>>>(W1w, Wcw, Wiw, Wfw);
    k_init<<<16, 256, 0, s_side>>>();
    // #4: GEMM (sampled by ncu), main stream
    k_s2h<<<dim3(MROWS / BM, GY), 512, STG * STGB>>>();

    // side chain (overlaps GEMM)
    k_tg1<<<16, 256, 0, s_side>>>(text);
    k_tg2<<<1, 1024, 0, s_side>>>();
    k_y_h<<<dim3(8, Lf), 256, 0, s_side>>>();
    k_pres<<<128, 256, 0, s_side>>>(W1w, W1b);
    for (int l = 0; l < NSTEP; l++) {
        k_step_s<<<128, 256, 0, s_side>>>(l);
        k_step_c<<<512, 256, 0, s_side>>>(Wcb, Wib, Wfb, bc, bi, bf);
    }
    k_qraw<<<512, 256, 0, s_side>>>(Wq);
    k_qln<<<1, 1024, 0, s_side>>>(lnw, lnb);
    k_av1<<<dim3(8, 8), 256, 0, s_side>>>();
    k_av2<<<16, 256, 0, s_side>>>();
    k_s13<<<MROWS / 8, 256, 0, s_side>>>();

    cudaEventRecord(ev_join, s_side);
    cudaStreamWaitEvent(0, ev_join, 0);

    k_score<<<Lf, 192>>>();
    k_topk<<<Lf, 256>>>();
    k_select<<<1, 32>>>();
    k_gather<<<64, 256>>>(proj, out);
}